// round 9
// baseline (speedup 1.0000x reference)
#include <cuda_runtime.h>
#include <cuda_bf16.h>
#include <math.h>

// Problem constants: B=2, C=128, H=W=128, outc=128, KS=3, N=9, PAD=1
#define Bn 2
#define Cn 128
#define Hh 128
#define Ww 128
#define OC 128

typedef unsigned long long u64;
typedef unsigned int u32;

// -------- scratch (static device globals; no allocation allowed) --------
__device__ float g_xt [Bn*Hh*Ww*Cn];                 // x as [B,H,W,C]
__device__ float g_om [Bn*Hh*Ww*27];                 // 18 offsets + 9 sigmoid(mask)
// w_conv per tap: hi tile (128 o-rows x 136 cols bf16) then lo tile; exact smem image
__device__ __align__(16) unsigned char g_wb2[9*2*34816];
// convA weights per tap: hi tile (32 o-rows x 136 cols bf16) then lo tile
__device__ __align__(16) unsigned char g_wcA[9*17408];

#define A_STRIDE_B 272              // 136 bf16 per row
#define A_HI_BYTES 17408            // 64 rows (deform A hi)
#define A_BUF_BYTES 34816           // hi + lo
#define B_TILE_BYTES 34816          // 128 rows (hi)
#define B_BUF_BYTES 69632           // hi + lo
#define D_B0_OFF (2 * 34816)        // 69632
#define D_SMEM (2*34816 + 2*69632)  // 208896

// convA (halo version)
#define CA_HALO_ROWS 324
#define CA_HALO_BYTES (324 * 272)   // 88128
#define CA_B_OFF (2 * 88128)        // 176256
#define CA_B_BYTES 17408
#define CA_SMEM (176256 + 2 * 17408) // 211072

__device__ __forceinline__ u32 smem_u32(const void* p) {
    u32 a;
    asm("{ .reg .u64 t; cvta.to.shared.u64 t, %1; cvt.u32.u64 %0, t; }" : "=r"(a) : "l"(p));
    return a;
}

__device__ __forceinline__ void ldm4(u32 addr, u32* r) {
    asm volatile("ldmatrix.sync.aligned.m8n8.x4.shared.b16 {%0,%1,%2,%3}, [%4];"
                 : "=r"(r[0]), "=r"(r[1]), "=r"(r[2]), "=r"(r[3]) : "r"(addr));
}

__device__ __forceinline__ void mma16816(float* c, const u32* a, u32 b0, u32 b1) {
    asm volatile("mma.sync.aligned.m16n8k16.row.col.f32.bf16.bf16.f32 "
                 "{%0,%1,%2,%3}, {%4,%5,%6,%7}, {%8,%9}, {%0,%1,%2,%3};"
                 : "+f"(c[0]), "+f"(c[1]), "+f"(c[2]), "+f"(c[3])
                 : "r"(a[0]), "r"(a[1]), "r"(a[2]), "r"(a[3]), "r"(b0), "r"(b1));
}

__device__ __forceinline__ void split_store(float4 sv, char* hiP, char* loP) {
    __nv_bfloat162 hA, hB, lA, lB;
    hA.x = __float2bfloat16(sv.x); hA.y = __float2bfloat16(sv.y);
    hB.x = __float2bfloat16(sv.z); hB.y = __float2bfloat16(sv.w);
    lA.x = __float2bfloat16(sv.x - __bfloat162float(hA.x));
    lA.y = __float2bfloat16(sv.y - __bfloat162float(hA.y));
    lB.x = __float2bfloat16(sv.z - __bfloat162float(hB.x));
    lB.y = __float2bfloat16(sv.w - __bfloat162float(hB.y));
    *(uint2*)hiP = make_uint2(*(u32*)&hA, *(u32*)&hB);
    *(uint2*)loP = make_uint2(*(u32*)&lA, *(u32*)&lB);
}

#define BAR_SYNC(id)   asm volatile("bar.sync %0, 512;"   :: "r"(id) : "memory")
#define BAR_ARRIVE(id) asm volatile("bar.arrive %0, 512;" :: "r"(id) : "memory")

// ---------------------------------------------------------------
// Kernel 0a: transpose x NCHW -> BHWC
__global__ void k_transpose_x(const float* __restrict__ x) {
    __shared__ float tile[32][33];
    int bxw = blockIdx.x, byc = blockIdx.y, bz = blockIdx.z;
    int b = bz >> 7, h = bz & 127;
    int tx = threadIdx.x, ty = threadIdx.y;
#pragma unroll
    for (int i = 0; i < 4; i++) {
        int c = byc * 32 + ty + i * 8;
        tile[ty + i * 8][tx] = x[((b * Cn + c) * Hh + h) * Ww + bxw * 32 + tx];
    }
    __syncthreads();
#pragma unroll
    for (int i = 0; i < 4; i++) {
        int w = bxw * 32 + ty + i * 8;
        g_xt[((b * Hh + h) * Ww + w) * Cn + byc * 32 + tx] = tile[tx][ty + i * 8];
    }
}

// ---------------------------------------------------------------
// Kernel 0b: weight re-layouts (bf16 hi/lo smem images for both GEMMs)
__global__ void k_transpose_w(const float* __restrict__ w_conv,
                              const float* __restrict__ w_p,
                              const float* __restrict__ w_m) {
    int t = blockIdx.x * blockDim.x + threadIdx.x;
    if (t < 9 * 128 * 128) {
        int c = t & 127;
        int o = (t >> 7) & 127;
        int k = t >> 14;
        int di = k / 3, dj = k - di * 3;
        float val = w_conv[((o * Cn + c) * 3 + di) * 3 + dj];
        __nv_bfloat16 hi = __float2bfloat16(val);
        __nv_bfloat16 lo = __float2bfloat16(val - __bfloat162float(hi));
        unsigned char* base = g_wb2 + k * B_BUF_BYTES;
        *(__nv_bfloat16*)(base + o * A_STRIDE_B + c * 2) = hi;
        *(__nv_bfloat16*)(base + B_TILE_BYTES + o * A_STRIDE_B + c * 2) = lo;
    } else {
        int t2 = t - 9 * 128 * 128;
        if (t2 < 9 * 27 * 128) {
            int c = t2 & 127;
            int rest = t2 >> 7;
            int o = rest % 27;
            int k = rest / 27;
            int kh = k / 3, kw = k - kh * 3;
            float val;
            if (o < 18) val = w_p[((o * Cn + c) * 3 + kh) * 3 + kw];
            else        val = w_m[(((o - 18) * Cn + c) * 3 + kh) * 3 + kw];
            __nv_bfloat16 hi = __float2bfloat16(val);
            __nv_bfloat16 lo = __float2bfloat16(val - __bfloat162float(hi));
            unsigned char* base = g_wcA + k * CA_B_BYTES;
            *(__nv_bfloat16*)(base + o * A_STRIDE_B + c * 2) = hi;
            *(__nv_bfloat16*)(base + 8704 + o * A_STRIDE_B + c * 2) = lo;
        }
    }
}

// stage tap-k convA weights (hi+lo, 17408 B = 1088 x 16B) via cp.async
__device__ __forceinline__ void cp_bA(u32 Bb, int k, int tid) {
    const char* src = (const char*)g_wcA + k * CA_B_BYTES;
#pragma unroll
    for (int i = 0; i < 3; i++) {
        int idx = tid + i * 512;
        if (idx < 1088) {
            asm volatile("cp.async.cg.shared.global [%0], [%1], 16;"
                         :: "r"(Bb + (u32)idx * 16u), "l"(src + idx * 16) : "memory");
        }
    }
    asm volatile("cp.async.commit_group;" ::: "memory");
}

// ---------------------------------------------------------------
// Kernel A: fused offset(18) + mask(9) 3x3 conv via bf16x3 mma.sync + smem halo.
__global__ void __launch_bounds__(512, 1) k_convA(const float* __restrict__ b_p,
                                                  const float* __restrict__ b_m) {
    extern __shared__ char smc[];
    u32 Ab = smem_u32(smc);
    u32 Bb = Ab + CA_B_OFF;

    int b  = blockIdx.z;
    int h0 = blockIdx.y * 16, w0 = blockIdx.x * 16;
    int tid = threadIdx.x;
    int lane = tid & 31, wid = tid >> 5;
    int mrow = wid * 16;

    const float4* xt4 = (const float4*)g_xt;

    cp_bA(Bb, 0, tid);

    for (int r = wid; r < CA_HALO_ROWS; r += 16) {
        int hy = r / 18, hx = r - hy * 18;
        int h = h0 - 1 + hy, w = w0 - 1 + hx;
        float4 sv = make_float4(0.f, 0.f, 0.f, 0.f);
        if (h >= 0 && h < Hh && w >= 0 && w < Ww)
            sv = xt4[((b * Hh + h) * Ww + w) * 32 + lane];
        u32 off = (u32)r * A_STRIDE_B + (u32)lane * 8u;
        split_store(sv, smc + off, smc + CA_HALO_BYTES + off);
    }
    asm volatile("cp.async.wait_group 0;" ::: "memory");
    __syncthreads();

    float acc[16];
#pragma unroll
    for (int i = 0; i < 16; i++) acc[i] = 0.f;

    int px_l = mrow + (lane & 15);
    int ly_l = px_l >> 4, lx_l = px_l & 15;
    u32 a_chunk = (u32)(lane >> 4) * 16u;
    u32 b_off = (u32)((lane & 7) + ((lane >> 4) << 3)) * A_STRIDE_B
              + (u32)((lane >> 3) & 1) * 16u;

#pragma unroll 1
    for (int t9 = 0; t9 < 9; t9++) {
        int kh = t9 / 3, kw = t9 - kh * 3;
        if (t9 < 8) cp_bA(Bb + (u32)(((t9 + 1) & 1) * CA_B_BYTES), t9 + 1, tid);
        u32 Bcur = Bb + (u32)((t9 & 1) * CA_B_BYTES);

        u32 hrow = (u32)((ly_l + kh) * 18 + lx_l + kw);
        u32 a_base = hrow * A_STRIDE_B + a_chunk;

#pragma unroll 1
        for (int kk = 0; kk < 8; kk++) {
            u32 koff = (u32)kk * 32u;
            u32 ah[4], al[4];
            ldm4(Ab + a_base + koff, ah);
            ldm4(Ab + (u32)CA_HALO_BYTES + a_base + koff, al);
#pragma unroll
            for (int ng = 0; ng < 2; ng++) {
                u32 bh[4], bl[4];
                u32 badd = Bcur + b_off + (u32)ng * (16u * A_STRIDE_B) + koff;
                ldm4(badd, bh);
                ldm4(badd + 8704u, bl);
                float* c0 = &acc[(ng * 2 + 0) * 4];
                float* c1 = &acc[(ng * 2 + 1) * 4];
                mma16816(c0, ah, bh[0], bh[1]);
                mma16816(c1, ah, bh[2], bh[3]);
                mma16816(c0, ah, bl[0], bl[1]);
                mma16816(c1, ah, bl[2], bl[3]);
                mma16816(c0, al, bh[0], bh[1]);
                mma16816(c1, al, bh[2], bh[3]);
            }
        }
        if (t9 < 8) {
            asm volatile("cp.async.wait_group 0;" ::: "memory");
            __syncthreads();
        }
    }
    __syncthreads();

    float* dsm = (float*)smc;
    {
        int g = lane >> 2, t = lane & 3;
#pragma unroll
        for (int si = 0; si < 4; si++) {
            int ob = si * 8;
            dsm[(mrow + g)     * 33 + ob + 2 * t]     = acc[si * 4 + 0];
            dsm[(mrow + g)     * 33 + ob + 2 * t + 1] = acc[si * 4 + 1];
            dsm[(mrow + g + 8) * 33 + ob + 2 * t]     = acc[si * 4 + 2];
            dsm[(mrow + g + 8) * 33 + ob + 2 * t + 1] = acc[si * 4 + 3];
        }
    }
    __syncthreads();
    for (int idx = tid; idx < 256 * 27; idx += 512) {
        int px = idx / 27, o = idx - px * 27;
        float val = dsm[px * 33 + o];
        int h = h0 + (px >> 4), w = w0 + (px & 15);
        float r;
        if (o < 18) r = val + b_p[o];
        else        r = 1.f / (1.f + expf(-(val + b_m[o - 18])));
        g_om[((b * Hh + h) * Ww + w) * 27 + o] = r;
    }
}

// ---------------------------------------------------------------
// Gather one conv-tap k for a 64-pixel tile: 8 producer warps x 8 px.
__device__ __forceinline__ void gather_tap8(int b, int k, int oh0, int ow0,
                                            int lane, int pwid,
                                            char* aHi, char* aLo) {
    const float4* xt4 = (const float4*)g_xt;
    int di = k / 3, dj = k - di * 3;
    int dh = (di == 0) ? -1 : 0;
    int iI = (di == 0) ? 2 : (di == 1 ? 0 : 1);
    int dw = (dj == 0) ? -1 : 0;
    int jJ = (dj == 0) ? 2 : (dj == 1 ? 0 : 1);
    int n = iI * 3 + jJ;
#pragma unroll 1
    for (int s = 0; s < 8; s++) {
        int px = pwid * 8 + s;
        int ly = px >> 4, lx = px & 15;
        int h = oh0 + ly + dh, w = ow0 + lx + dw;
        float4 sv;
        if (h < 0 || w < 0) {
            sv = make_float4(0.f, 0.f, 0.f, 0.f);
        } else {
            const float* om = &g_om[((b * Hh + h) * Ww + w) * 27];
            float offx = om[n], offy = om[9 + n], mval = om[18 + n];
            float p_x = offx + (float)(iI - 1) + (float)(h + 1);
            float p_y = offy + (float)(jJ - 1) + (float)(w + 1);
            float flx = floorf(p_x), fly = floorf(p_y);
            float ltx = fminf(fmaxf(flx, 0.f), 129.f);
            float lty = fminf(fmaxf(fly, 0.f), 129.f);
            float rbx = fminf(fmaxf(flx + 1.f, 0.f), 129.f);
            float rby = fminf(fmaxf(fly + 1.f, 0.f), 129.f);
            float cpx = fminf(fmaxf(p_x, 0.f), 129.f);
            float cpy = fminf(fmaxf(p_y, 0.f), 129.f);
            float ax  = 1.f + (ltx - cpx);
            float bx_ = 1.f - (rbx - cpx);
            float ay  = 1.f + (lty - cpy);
            float by_ = 1.f - (rby - cpy);
            float wq[4] = { ax * ay * mval, bx_ * by_ * mval, ax * by_ * mval, bx_ * ay * mval };
            float qxf[4] = { ltx, rbx, ltx, rbx };
            float qyf[4] = { lty, rby, rby, lty };
            int base4[4];
#pragma unroll
            for (int j = 0; j < 4; j++) {
                int ix = (int)qxf[j], iy = (int)qyf[j];
                bool valid = (ix >= 1 && ix <= Hh && iy >= 1 && iy <= Ww);
                base4[j] = valid ? (((b * Hh + ix - 1) * Ww + iy - 1) * 32) : 0;
                if (!valid) wq[j] = 0.f;
            }
            float4 a0 = xt4[base4[0] + lane];
            float4 a1 = xt4[base4[1] + lane];
            float4 a2 = xt4[base4[2] + lane];
            float4 a3 = xt4[base4[3] + lane];
            sv.x = wq[0]*a0.x + wq[1]*a1.x + wq[2]*a2.x + wq[3]*a3.x;
            sv.y = wq[0]*a0.y + wq[1]*a1.y + wq[2]*a2.y + wq[3]*a3.y;
            sv.z = wq[0]*a0.z + wq[1]*a1.z + wq[2]*a2.z + wq[3]*a3.z;
            sv.w = wq[0]*a0.w + wq[1]*a1.w + wq[2]*a2.w + wq[3]*a3.w;
        }
        u32 off = (u32)px * A_STRIDE_B + (u32)lane * 8u;
        split_store(sv, aHi + off, aLo + off);
    }
}

// ---------------------------------------------------------------
// Kernel B: warp-specialized deformable gather -> bf16x3 mma.sync GEMM.
// 512 thr: warps 0-7 consumers (MMA), warps 8-15 producers (B cp.async + gather).
// A and B double-buffered: producers fill tap k while consumers MMA tap k-1.
// smem: A0(34816) A1(34816) B0(69632) B1(69632) = 208896. 1 CTA/SM.
__global__ void __launch_bounds__(512, 1) k_deform(float* __restrict__ out) {
    extern __shared__ char smc[];
    u32 Ab = smem_u32(smc);
    u32 Bb = Ab + D_B0_OFF;

    int b   = blockIdx.z;
    int oh0 = blockIdx.y * 4, ow0 = blockIdx.x * 16;
    int tid  = threadIdx.x;
    int lane = tid & 31, wid = tid >> 5;

    if (wid >= 8) {
        // ---------------- producers ----------------
        int pwid = wid - 8;
        int ptid = tid - 256;
#pragma unroll 1
        for (int fill = 0; fill < 9; fill++) {
            int bp = fill & 1;
            if (fill >= 2) BAR_SYNC(3 + bp);          // consumers done with this buffer
            // stage B[fill] (69632 B = 4352 x 16B) over 256 producer threads
            {
                const char* src = (const char*)g_wb2 + fill * B_BUF_BYTES;
                u32 dst = Bb + (u32)bp * (u32)B_BUF_BYTES;
#pragma unroll
                for (int i = 0; i < 17; i++) {
                    int idx = ptid + i * 256;
                    asm volatile("cp.async.cg.shared.global [%0], [%1], 16;"
                                 :: "r"(dst + (u32)idx * 16u), "l"(src + idx * 16) : "memory");
                }
                asm volatile("cp.async.commit_group;" ::: "memory");
            }
            gather_tap8(b, fill, oh0, ow0, lane, pwid,
                        smc + bp * A_BUF_BYTES, smc + bp * A_BUF_BYTES + A_HI_BYTES);
            asm volatile("cp.async.wait_group 0;" ::: "memory");
            BAR_ARRIVE(1 + bp);                       // buffer full
        }
        return;
    }

    // ---------------- consumers ----------------
    int mrow = (wid & 3) * 16;
    int nb   = (wid >> 2) * 64;

    float acc[32];
#pragma unroll
    for (int i = 0; i < 32; i++) acc[i] = 0.f;

    u32 a_off = (u32)(mrow + (lane & 15)) * A_STRIDE_B + (u32)(lane >> 4) * 16u;
    u32 b_off = (u32)(nb + (lane & 7) + ((lane >> 4) << 3)) * A_STRIDE_B
              + (u32)((lane >> 3) & 1) * 16u;

#pragma unroll 1
    for (int k = 0; k < 9; k++) {
        int bp = k & 1;
        BAR_SYNC(1 + bp);                             // wait buffer full
        u32 Acur = Ab + (u32)bp * (u32)A_BUF_BYTES;
        u32 Bcur = Bb + (u32)bp * (u32)B_BUF_BYTES;

#pragma unroll 1
        for (int kk = 0; kk < 8; kk++) {
            u32 koff = (u32)kk * 32u;
            u32 ah[4], al[4];
            ldm4(Acur + a_off + koff, ah);
            ldm4(Acur + (u32)A_HI_BYTES + a_off + koff, al);
#pragma unroll
            for (int ng = 0; ng < 4; ng++) {
                u32 bh[4], bl[4];
                u32 badd = Bcur + b_off + (u32)ng * (16u * A_STRIDE_B) + koff;
                ldm4(badd, bh);
                ldm4(badd + (u32)B_TILE_BYTES, bl);
                float* c0 = &acc[(ng * 2 + 0) * 4];
                float* c1 = &acc[(ng * 2 + 1) * 4];
                mma16816(c0, ah, bh[0], bh[1]);
                mma16816(c1, ah, bh[2], bh[3]);
                mma16816(c0, ah, bl[0], bl[1]);
                mma16816(c1, ah, bl[2], bl[3]);
                mma16816(c0, al, bh[0], bh[1]);
                mma16816(c1, al, bh[2], bh[3]);
            }
        }
        BAR_ARRIVE(3 + bp);                           // buffer free
    }

    // epilogue: direct global stores (32B-sector coalesced)
    {
        int g = lane >> 2, t = lane & 3;
        int oh = oh0 + (mrow >> 4);
        int ow1 = ow0 + g, ow2 = ow0 + g + 8;
#pragma unroll
        for (int si = 0; si < 8; si++) {
            int o0 = nb + si * 8 + 2 * t;
            float* r0 = &out[((b * OC + o0) * Hh + oh) * Ww];
            float* r1 = &out[((b * OC + o0 + 1) * Hh + oh) * Ww];
            r0[ow1] = acc[si * 4 + 0];
            r1[ow1] = acc[si * 4 + 1];
            r0[ow2] = acc[si * 4 + 2];
            r1[ow2] = acc[si * 4 + 3];
        }
    }
}

// ---------------------------------------------------------------
extern "C" void kernel_launch(void* const* d_in, const int* in_sizes, int n_in,
                              void* d_out, int out_size) {
    const float* x      = (const float*)d_in[0];
    const float* w_p    = (const float*)d_in[1];
    const float* b_p    = (const float*)d_in[2];
    const float* w_m    = (const float*)d_in[3];
    const float* b_m    = (const float*)d_in[4];
    const float* w_conv = (const float*)d_in[5];
    float* out = (float*)d_out;

    cudaFuncSetAttribute(k_convA,  cudaFuncAttributeMaxDynamicSharedMemorySize, CA_SMEM);
    cudaFuncSetAttribute(k_deform, cudaFuncAttributeMaxDynamicSharedMemorySize, D_SMEM);

    k_transpose_x<<<dim3(4, 4, Bn * Hh), dim3(32, 8)>>>(x);

    int wthreads = 9 * 128 * 128 + 9 * 27 * 128;
    k_transpose_w<<<(wthreads + 255) / 256, 256>>>(w_conv, w_p, w_m);

    // convA: tile 16x16: grid (8, 8, B) = 128 CTAs
    k_convA<<<dim3(8, 8, Bn), 512, CA_SMEM>>>(b_p, b_m);

    // deform: tile 4(h) x 16(w): grid (8, 32, B) = 512 CTAs
    k_deform<<<dim3(8, 32, Bn), 512, D_SMEM>>>(out);
}

// round 10
// speedup vs baseline: 1.8420x; 1.8420x over previous
#include <cuda_runtime.h>
#include <cuda_fp16.h>
#include <math.h>

// Problem constants: B=2, C=128, H=W=128, outc=128, KS=3, N=9, PAD=1
#define Bn 2
#define Cn 128
#define Hh 128
#define Ww 128
#define OC 128

typedef unsigned long long u64;
typedef unsigned int u32;

// -------- scratch (static device globals; no allocation allowed) --------
__device__ __half g_xt [Bn*Hh*Ww*Cn];              // x as fp16 [B,H,W,C]
__device__ float  g_om [Bn*Hh*Ww*27];              // 18 offsets + 9 sigmoid(mask)
__device__ __align__(16) __half g_wd[9*128*136];   // deform W fp16 [k][o][c], row stride 136
__device__ __align__(16) __half g_wa[9*32*136];    // convA W fp16 [k][o(27)][c]; rows 27-31 zero

#define STRIDE_B 272                 // 136 fp16 per row
#define D_A_BYTES 17408              // 64 rows
#define D_B_BYTES 34816              // 128 rows
#define D_SMEM (2*17408 + 2*34816)   // 104448  (A0 A1 B0 B1)

#define CA_HALO_BYTES (180*272)      // 48960 (10h x 18w halo rows)
#define CA_B_BYTES 8704              // 32 rows
#define CA_SMEM (48960 + 2*8704)     // 66368

__device__ __forceinline__ u32 smem_u32(const void* p) {
    u32 a;
    asm("{ .reg .u64 t; cvta.to.shared.u64 t, %1; cvt.u32.u64 %0, t; }" : "=r"(a) : "l"(p));
    return a;
}

__device__ __forceinline__ void ldm4(u32 addr, u32* r) {
    asm volatile("ldmatrix.sync.aligned.m8n8.x4.shared.b16 {%0,%1,%2,%3}, [%4];"
                 : "=r"(r[0]), "=r"(r[1]), "=r"(r[2]), "=r"(r[3]) : "r"(addr));
}

__device__ __forceinline__ void mma16816f(float* c, const u32* a, u32 b0, u32 b1) {
    asm volatile("mma.sync.aligned.m16n8k16.row.col.f32.f16.f16.f32 "
                 "{%0,%1,%2,%3}, {%4,%5,%6,%7}, {%8,%9}, {%0,%1,%2,%3};"
                 : "+f"(c[0]), "+f"(c[1]), "+f"(c[2]), "+f"(c[3])
                 : "r"(a[0]), "r"(a[1]), "r"(a[2]), "r"(a[3]), "r"(b0), "r"(b1));
}

// ---------------------------------------------------------------
// Kernel 0a: transpose x NCHW -> BHWC (fp16 output)
__global__ void k_transpose_x(const float* __restrict__ x) {
    __shared__ float tile[32][33];
    int bxw = blockIdx.x, byc = blockIdx.y, bz = blockIdx.z;
    int b = bz >> 7, h = bz & 127;
    int tx = threadIdx.x, ty = threadIdx.y;
#pragma unroll
    for (int i = 0; i < 4; i++) {
        int c = byc * 32 + ty + i * 8;
        tile[ty + i * 8][tx] = x[((b * Cn + c) * Hh + h) * Ww + bxw * 32 + tx];
    }
    __syncthreads();
#pragma unroll
    for (int i = 0; i < 4; i++) {
        int w = bxw * 32 + ty + i * 8;
        g_xt[((b * Hh + h) * Ww + w) * Cn + byc * 32 + tx] = __float2half(tile[tx][ty + i * 8]);
    }
}

// ---------------------------------------------------------------
// Kernel 0b: weight re-layouts (fp16 ldmatrix row images)
__global__ void k_transpose_w(const float* __restrict__ w_conv,
                              const float* __restrict__ w_p,
                              const float* __restrict__ w_m) {
    int t = blockIdx.x * blockDim.x + threadIdx.x;
    if (t < 9 * 128 * 128) {
        int c = t & 127;
        int o = (t >> 7) & 127;
        int k = t >> 14;
        int di = k / 3, dj = k - di * 3;
        float val = w_conv[((o * Cn + c) * 3 + di) * 3 + dj];
        g_wd[(k * 128 + o) * 136 + c] = __float2half(val);
    } else {
        int t2 = t - 9 * 128 * 128;
        if (t2 < 9 * 27 * 128) {
            int c = t2 & 127;
            int rest = t2 >> 7;
            int o = rest % 27;
            int k = rest / 27;
            int kh = k / 3, kw = k - kh * 3;
            float val;
            if (o < 18) val = w_p[((o * Cn + c) * 3 + kh) * 3 + kw];
            else        val = w_m[(((o - 18) * Cn + c) * 3 + kh) * 3 + kw];
            g_wa[(k * 32 + o) * 136 + c] = __float2half(val);
        }
    }
}

// stage tap-k convA weights (8704 B = 544 x 16B) via cp.async (256 thr)
__device__ __forceinline__ void cp_bA(u32 dst, int k, int tid) {
    const char* src = (const char*)g_wa + k * CA_B_BYTES;
#pragma unroll
    for (int i = 0; i < 3; i++) {
        int idx = tid + i * 256;
        if (idx < 544) {
            asm volatile("cp.async.cg.shared.global [%0], [%1], 16;"
                         :: "r"(dst + (u32)idx * 16u), "l"(src + idx * 16) : "memory");
        }
    }
    asm volatile("cp.async.commit_group;" ::: "memory");
}

// stage tap-k deform weights (34816 B = 2176 x 16B) via cp.async (512 thr)
__device__ __forceinline__ void cp_bD(u32 dst, int k, int tid) {
    const char* src = (const char*)g_wd + k * D_B_BYTES;
#pragma unroll
    for (int i = 0; i < 5; i++) {
        int idx = tid + i * 512;
        if (idx < 2176) {
            asm volatile("cp.async.cg.shared.global [%0], [%1], 16;"
                         :: "r"(dst + (u32)idx * 16u), "l"(src + idx * 16) : "memory");
        }
    }
    asm volatile("cp.async.commit_group;" ::: "memory");
}

// ---------------------------------------------------------------
// Kernel A: fused offset(18)+mask(9) 3x3 conv, fp16 single-term mma + smem halo.
// Block 256 / 8 warps; tile M=128 px (8h x 16w) x N=32 (27 used).
// Halo 10x18 rows copied once (fp16, no conversion); B double-buffered.
__global__ void __launch_bounds__(256, 2) k_convA(const float* __restrict__ b_p,
                                                  const float* __restrict__ b_m) {
    extern __shared__ char smc[];
    u32 Sb = smem_u32(smc);
    u32 Bbase = Sb + CA_HALO_BYTES;

    int b  = blockIdx.z;
    int h0 = blockIdx.y * 8, w0 = blockIdx.x * 16;
    int tid = threadIdx.x;
    int lane = tid & 31, wid = tid >> 5;   // 8 warps

    cp_bA(Bbase, 0, tid);

    // halo copy: 180 rows, fp16 direct (lane -> 4 channels = 8B)
    const uint2* xt2 = (const uint2*)g_xt;
    for (int r = wid; r < 180; r += 8) {
        int hy = r / 18, hx = r - hy * 18;
        int h = h0 - 1 + hy, w = w0 - 1 + hx;
        uint2 v = make_uint2(0u, 0u);
        if (h >= 0 && h < Hh && w >= 0 && w < Ww)
            v = xt2[((b * Hh + h) * Ww + w) * 32 + lane];
        *(uint2*)(smc + r * STRIDE_B + lane * 8) = v;
    }
    asm volatile("cp.async.wait_group 0;" ::: "memory");
    __syncthreads();

    float acc[16];
#pragma unroll
    for (int i = 0; i < 16; i++) acc[i] = 0.f;

    int mrow = wid * 16;
    int px_l = mrow + (lane & 15);
    int ly_l = px_l >> 4, lx_l = px_l & 15;
    u32 a_chunk = (u32)(lane >> 4) * 16u;
    u32 b_off = (u32)((lane & 7) + ((lane >> 4) << 3)) * STRIDE_B
              + (u32)((lane >> 3) & 1) * 16u;

#pragma unroll 1
    for (int t9 = 0; t9 < 9; t9++) {
        int kh = t9 / 3, kw = t9 - kh * 3;
        if (t9 < 8) cp_bA(Bbase + (u32)(((t9 + 1) & 1) * CA_B_BYTES), t9 + 1, tid);
        u32 Bcur = Bbase + (u32)((t9 & 1) * CA_B_BYTES);
        u32 a_base = (u32)((ly_l + kh) * 18 + lx_l + kw) * STRIDE_B + a_chunk;

#pragma unroll 1
        for (int kk = 0; kk < 8; kk++) {
            u32 koff = (u32)kk * 32u;
            u32 a[4], b0[4], b1[4];
            ldm4(Sb + a_base + koff, a);
            ldm4(Bcur + b_off + koff, b0);
            ldm4(Bcur + b_off + 16u * STRIDE_B + koff, b1);
            mma16816f(acc + 0,  a, b0[0], b0[1]);
            mma16816f(acc + 4,  a, b0[2], b0[3]);
            mma16816f(acc + 8,  a, b1[0], b1[1]);
            mma16816f(acc + 12, a, b1[2], b1[3]);
        }
        if (t9 < 8) {
            asm volatile("cp.async.wait_group 0;" ::: "memory");
            __syncthreads();
        }
    }
    __syncthreads();

    // epilogue: frags -> dsm[px][33] -> bias/sigmoid -> g_om (dsm overlays halo)
    float* dsm = (float*)smc;
    {
        int g = lane >> 2, t = lane & 3;
#pragma unroll
        for (int si = 0; si < 4; si++) {
            int ob = si * 8;
            dsm[(mrow + g)     * 33 + ob + 2 * t]     = acc[si * 4 + 0];
            dsm[(mrow + g)     * 33 + ob + 2 * t + 1] = acc[si * 4 + 1];
            dsm[(mrow + g + 8) * 33 + ob + 2 * t]     = acc[si * 4 + 2];
            dsm[(mrow + g + 8) * 33 + ob + 2 * t + 1] = acc[si * 4 + 3];
        }
    }
    __syncthreads();
    for (int idx = tid; idx < 128 * 27; idx += 256) {
        int px = idx / 27, o = idx - px * 27;
        float val = dsm[px * 33 + o];
        int h = h0 + (px >> 4), w = w0 + (px & 15);
        float r;
        if (o < 18) r = val + b_p[o];
        else        r = 1.f / (1.f + expf(-(val + b_m[o - 18])));
        g_om[((b * Hh + h) * Ww + w) * 27 + o] = r;
    }
}

// ---------------------------------------------------------------
// Deform gather (fp16): one conv-tap k for a 64-px tile; 16 warps x 4 px.
__device__ __forceinline__ void gather_tapD(int b, int k, int oh0, int ow0,
                                            int lane, int wid, char* Adst) {
    const uint2* xt2 = (const uint2*)g_xt;
    int di = k / 3, dj = k - di * 3;
    int dh = (di == 0) ? -1 : 0;
    int iI = (di == 0) ? 2 : (di == 1 ? 0 : 1);
    int dw = (dj == 0) ? -1 : 0;
    int jJ = (dj == 0) ? 2 : (dj == 1 ? 0 : 1);
    int n = iI * 3 + jJ;
#pragma unroll 2
    for (int s = 0; s < 4; s++) {
        int px = wid * 4 + s;
        int ly = px >> 4, lx = px & 15;
        int h = oh0 + ly + dh, w = ow0 + lx + dw;
        float4 sv = make_float4(0.f, 0.f, 0.f, 0.f);
        if (h >= 0 && w >= 0) {
            const float* om = &g_om[((b * Hh + h) * Ww + w) * 27];
            float offx = om[n], offy = om[9 + n], mval = om[18 + n];
            float p_x = offx + (float)(iI - 1) + (float)(h + 1);
            float p_y = offy + (float)(jJ - 1) + (float)(w + 1);
            float flx = floorf(p_x), fly = floorf(p_y);
            float ltx = fminf(fmaxf(flx, 0.f), 129.f);
            float lty = fminf(fmaxf(fly, 0.f), 129.f);
            float rbx = fminf(fmaxf(flx + 1.f, 0.f), 129.f);
            float rby = fminf(fmaxf(fly + 1.f, 0.f), 129.f);
            float cpx = fminf(fmaxf(p_x, 0.f), 129.f);
            float cpy = fminf(fmaxf(p_y, 0.f), 129.f);
            float ax  = 1.f + (ltx - cpx);
            float bx_ = 1.f - (rbx - cpx);
            float ay  = 1.f + (lty - cpy);
            float by_ = 1.f - (rby - cpy);
            float wq[4] = { ax * ay * mval, bx_ * by_ * mval, ax * by_ * mval, bx_ * ay * mval };
            float qxf[4] = { ltx, rbx, ltx, rbx };
            float qyf[4] = { lty, rby, rby, lty };
#pragma unroll
            for (int j = 0; j < 4; j++) {
                int ix = (int)qxf[j], iy = (int)qyf[j];
                bool valid = (ix >= 1 && ix <= Hh && iy >= 1 && iy <= Ww);
                int base = valid ? (((b * Hh + ix - 1) * Ww + iy - 1) * 32) : 0;
                float wj = valid ? wq[j] : 0.f;
                uint2 q = xt2[base + lane];
                __half2 p0 = *(__half2*)&q.x;
                __half2 p1 = *(__half2*)&q.y;
                float2 f0 = __half22float2(p0);
                float2 f1 = __half22float2(p1);
                sv.x += wj * f0.x; sv.y += wj * f0.y;
                sv.z += wj * f1.x; sv.w += wj * f1.y;
            }
        }
        __half2 o0 = __floats2half2_rn(sv.x, sv.y);
        __half2 o1 = __floats2half2_rn(sv.z, sv.w);
        *(uint2*)(Adst + px * STRIDE_B + lane * 8) = make_uint2(*(u32*)&o0, *(u32*)&o1);
    }
}

// Deform MMA for one tap: warp = 16px x 32o, fp16 single term.
__device__ __forceinline__ void mma_tapD(u32 Acur, u32 Bcur, u32 a_off, u32 b_off,
                                         float* acc) {
#pragma unroll 1
    for (int kk = 0; kk < 8; kk++) {
        u32 koff = (u32)kk * 32u;
        u32 a[4], b0[4], b1[4];
        ldm4(Acur + a_off + koff, a);
        ldm4(Bcur + b_off + koff, b0);
        ldm4(Bcur + b_off + 16u * STRIDE_B + koff, b1);
        mma16816f(acc + 0,  a, b0[0], b0[1]);
        mma16816f(acc + 4,  a, b0[2], b0[3]);
        mma16816f(acc + 8,  a, b1[0], b1[1]);
        mma16816f(acc + 12, a, b1[2], b1[3]);
    }
}

// ---------------------------------------------------------------
// Kernel B: deformable gather -> fp16 mma.sync GEMM, fully double-buffered.
// Block 512 / 16 warps; tile M=64 px (4h x 16w) x N=128 o; 2 CTAs/SM.
// Per tap: odd warps gather(k+1) then MMA(k); even warps MMA(k) then gather(k+1).
// smem: A0 A1 (2x17408) + B0 B1 (2x34816) = 104448.
__global__ void __launch_bounds__(512, 2) k_deform(float* __restrict__ out) {
    extern __shared__ char smc[];
    u32 Sb = smem_u32(smc);
    u32 Bbase = Sb + 2 * D_A_BYTES;

    int b   = blockIdx.z;
    int oh0 = blockIdx.y * 4, ow0 = blockIdx.x * 16;
    int tid  = threadIdx.x;
    int lane = tid & 31, wid = tid >> 5;
    int mrow = (wid & 3) * 16;
    int nb   = (wid >> 2) * 32;

    float acc[16];
#pragma unroll
    for (int i = 0; i < 16; i++) acc[i] = 0.f;

    u32 a_off = (u32)(mrow + (lane & 15)) * STRIDE_B + (u32)(lane >> 4) * 16u;
    u32 b_off = (u32)(nb + (lane & 7) + ((lane >> 4) << 3)) * STRIDE_B
              + (u32)((lane >> 3) & 1) * 16u;

    // prologue: tap 0 into A0/B0
    cp_bD(Bbase, 0, tid);
    gather_tapD(b, 0, oh0, ow0, lane, wid, smc);
    asm volatile("cp.async.wait_group 0;" ::: "memory");
    __syncthreads();

#pragma unroll 1
    for (int k = 0; k < 9; k++) {
        int cur = k & 1;
        u32 Acur = Sb + (u32)cur * D_A_BYTES;
        u32 Bcur = Bbase + (u32)cur * D_B_BYTES;
        char* Anxt = smc + (cur ^ 1) * D_A_BYTES;

        if (k < 8) cp_bD(Bbase + (u32)(cur ^ 1) * D_B_BYTES, k + 1, tid);

        if (wid & 1) {
            if (k < 8) gather_tapD(b, k + 1, oh0, ow0, lane, wid, Anxt);
            mma_tapD(Acur, Bcur, a_off, b_off, acc);
        } else {
            mma_tapD(Acur, Bcur, a_off, b_off, acc);
            if (k < 8) gather_tapD(b, k + 1, oh0, ow0, lane, wid, Anxt);
        }
        if (k < 8) asm volatile("cp.async.wait_group 0;" ::: "memory");
        __syncthreads();
    }

    // epilogue: direct global stores
    {
        int g = lane >> 2, t = lane & 3;
        int oh = oh0 + (mrow >> 4);
        int ow1 = ow0 + g, ow2 = ow0 + g + 8;
#pragma unroll
        for (int si = 0; si < 4; si++) {
            int o0 = nb + si * 8 + 2 * t;
            float* r0 = &out[((b * OC + o0) * Hh + oh) * Ww];
            float* r1 = &out[((b * OC + o0 + 1) * Hh + oh) * Ww];
            r0[ow1] = acc[si * 4 + 0];
            r1[ow1] = acc[si * 4 + 1];
            r0[ow2] = acc[si * 4 + 2];
            r1[ow2] = acc[si * 4 + 3];
        }
    }
}

// ---------------------------------------------------------------
extern "C" void kernel_launch(void* const* d_in, const int* in_sizes, int n_in,
                              void* d_out, int out_size) {
    const float* x      = (const float*)d_in[0];
    const float* w_p    = (const float*)d_in[1];
    const float* b_p    = (const float*)d_in[2];
    const float* w_m    = (const float*)d_in[3];
    const float* b_m    = (const float*)d_in[4];
    const float* w_conv = (const float*)d_in[5];
    float* out = (float*)d_out;

    cudaFuncSetAttribute(k_convA,  cudaFuncAttributeMaxDynamicSharedMemorySize, CA_SMEM);
    cudaFuncSetAttribute(k_deform, cudaFuncAttributeMaxDynamicSharedMemorySize, D_SMEM);

    k_transpose_x<<<dim3(4, 4, Bn * Hh), dim3(32, 8)>>>(x);

    int wthreads = 9 * 128 * 128 + 9 * 27 * 128;
    k_transpose_w<<<(wthreads + 255) / 256, 256>>>(w_conv, w_p, w_m);

    // convA: tile 8(h) x 16(w): grid (8, 16, B) = 256 CTAs
    k_convA<<<dim3(8, 16, Bn), 256, CA_SMEM>>>(b_p, b_m);

    // deform: tile 4(h) x 16(w): grid (8, 32, B) = 512 CTAs
    k_deform<<<dim3(8, 32, Bn), 512, D_SMEM>>>(out);
}

// round 11
// speedup vs baseline: 2.1541x; 1.1695x over previous
#include <cuda_runtime.h>
#include <cuda_fp16.h>
#include <math.h>

// Problem constants: B=2, C=128, H=W=128, outc=128, KS=3, N=9, PAD=1
#define Bn 2
#define Cn 128
#define Hh 128
#define Ww 128
#define OC 128

typedef unsigned long long u64;
typedef unsigned int u32;

// -------- scratch (static device globals; no allocation allowed) --------
__device__ __half g_xt [Bn*Hh*Ww*Cn];              // x as fp16 [B,H,W,C]
// per (b,h,w,n) gather meta: {int4 base(in uint2 units), float4 wq} = 32B
__device__ __align__(16) int g_meta[Bn*Hh*Ww*9*8]; // 9.4 MB
__device__ __align__(16) __half g_wd[9*128*136];   // deform W fp16 [k][o][c], row stride 136
__device__ __align__(16) __half g_wa[9*32*136];    // convA W fp16 [k][o(27)][c]; rows 27-31 zero

#define STRIDE_B 272                 // 136 fp16 per row
#define D_A_BYTES 17408              // 64 rows
#define D_B_BYTES 34816              // 128 rows
#define D_SMEM (2*17408 + 2*34816)   // 104448  (A0 A1 B0 B1)

#define CA_HALO_BYTES (180*272)      // 48960 (10h x 18w halo rows)
#define CA_B_BYTES 8704              // 32 rows
#define CA_SMEM (48960 + 2*8704)     // 66368

__device__ __forceinline__ u32 smem_u32(const void* p) {
    u32 a;
    asm("{ .reg .u64 t; cvta.to.shared.u64 t, %1; cvt.u32.u64 %0, t; }" : "=r"(a) : "l"(p));
    return a;
}

__device__ __forceinline__ void ldm4(u32 addr, u32* r) {
    asm volatile("ldmatrix.sync.aligned.m8n8.x4.shared.b16 {%0,%1,%2,%3}, [%4];"
                 : "=r"(r[0]), "=r"(r[1]), "=r"(r[2]), "=r"(r[3]) : "r"(addr));
}

__device__ __forceinline__ void mma16816f(float* c, const u32* a, u32 b0, u32 b1) {
    asm volatile("mma.sync.aligned.m16n8k16.row.col.f32.f16.f16.f32 "
                 "{%0,%1,%2,%3}, {%4,%5,%6,%7}, {%8,%9}, {%0,%1,%2,%3};"
                 : "+f"(c[0]), "+f"(c[1]), "+f"(c[2]), "+f"(c[3])
                 : "r"(a[0]), "r"(a[1]), "r"(a[2]), "r"(a[3]), "r"(b0), "r"(b1));
}

// ---------------------------------------------------------------
// Kernel 0a: transpose x NCHW -> BHWC (fp16 output)
__global__ void k_transpose_x(const float* __restrict__ x) {
    __shared__ float tile[32][33];
    int bxw = blockIdx.x, byc = blockIdx.y, bz = blockIdx.z;
    int b = bz >> 7, h = bz & 127;
    int tx = threadIdx.x, ty = threadIdx.y;
#pragma unroll
    for (int i = 0; i < 4; i++) {
        int c = byc * 32 + ty + i * 8;
        tile[ty + i * 8][tx] = x[((b * Cn + c) * Hh + h) * Ww + bxw * 32 + tx];
    }
    __syncthreads();
#pragma unroll
    for (int i = 0; i < 4; i++) {
        int w = bxw * 32 + ty + i * 8;
        g_xt[((b * Hh + h) * Ww + w) * Cn + byc * 32 + tx] = __float2half(tile[tx][ty + i * 8]);
    }
}

// ---------------------------------------------------------------
// Kernel 0b: weight re-layouts (fp16 ldmatrix row images)
__global__ void k_transpose_w(const float* __restrict__ w_conv,
                              const float* __restrict__ w_p,
                              const float* __restrict__ w_m) {
    int t = blockIdx.x * blockDim.x + threadIdx.x;
    if (t < 9 * 128 * 128) {
        int c = t & 127;
        int o = (t >> 7) & 127;
        int k = t >> 14;
        int di = k / 3, dj = k - di * 3;
        float val = w_conv[((o * Cn + c) * 3 + di) * 3 + dj];
        g_wd[(k * 128 + o) * 136 + c] = __float2half(val);
    } else {
        int t2 = t - 9 * 128 * 128;
        if (t2 < 9 * 27 * 128) {
            int c = t2 & 127;
            int rest = t2 >> 7;
            int o = rest % 27;
            int k = rest / 27;
            int kh = k / 3, kw = k - kh * 3;
            float val;
            if (o < 18) val = w_p[((o * Cn + c) * 3 + kh) * 3 + kw];
            else        val = w_m[(((o - 18) * Cn + c) * 3 + kh) * 3 + kw];
            g_wa[(k * 32 + o) * 136 + c] = __float2half(val);
        }
    }
}

// stage tap-k convA weights (8704 B = 544 x 16B) via cp.async (256 thr)
__device__ __forceinline__ void cp_bA(u32 dst, int k, int tid) {
    const char* src = (const char*)g_wa + k * CA_B_BYTES;
#pragma unroll
    for (int i = 0; i < 3; i++) {
        int idx = tid + i * 256;
        if (idx < 544) {
            asm volatile("cp.async.cg.shared.global [%0], [%1], 16;"
                         :: "r"(dst + (u32)idx * 16u), "l"(src + idx * 16) : "memory");
        }
    }
    asm volatile("cp.async.commit_group;" ::: "memory");
}

// stage tap-k deform weights (34816 B = 2176 x 16B) via cp.async (512 thr)
__device__ __forceinline__ void cp_bD(u32 dst, int k, int tid) {
    const char* src = (const char*)g_wd + k * D_B_BYTES;
#pragma unroll
    for (int i = 0; i < 5; i++) {
        int idx = tid + i * 512;
        if (idx < 2176) {
            asm volatile("cp.async.cg.shared.global [%0], [%1], 16;"
                         :: "r"(dst + (u32)idx * 16u), "l"(src + idx * 16) : "memory");
        }
    }
    asm volatile("cp.async.commit_group;" ::: "memory");
}

// ---------------------------------------------------------------
// Kernel A: fused offset(18)+mask(9) 3x3 conv (fp16 mma + smem halo),
// epilogue computes the full deformable-gather metadata per (px, n):
// 4 bilinear base addresses + 4 modulated weights -> g_meta.
__global__ void __launch_bounds__(256, 2) k_convA(const float* __restrict__ b_p,
                                                  const float* __restrict__ b_m) {
    extern __shared__ char smc[];
    u32 Sb = smem_u32(smc);
    u32 Bbase = Sb + CA_HALO_BYTES;

    int b  = blockIdx.z;
    int h0 = blockIdx.y * 8, w0 = blockIdx.x * 16;
    int tid = threadIdx.x;
    int lane = tid & 31, wid = tid >> 5;   // 8 warps

    cp_bA(Bbase, 0, tid);

    // halo copy: 180 rows, fp16 direct (lane -> 4 channels = 8B)
    const uint2* xt2 = (const uint2*)g_xt;
    for (int r = wid; r < 180; r += 8) {
        int hy = r / 18, hx = r - hy * 18;
        int h = h0 - 1 + hy, w = w0 - 1 + hx;
        uint2 v = make_uint2(0u, 0u);
        if (h >= 0 && h < Hh && w >= 0 && w < Ww)
            v = xt2[((b * Hh + h) * Ww + w) * 32 + lane];
        *(uint2*)(smc + r * STRIDE_B + lane * 8) = v;
    }
    asm volatile("cp.async.wait_group 0;" ::: "memory");
    __syncthreads();

    float acc[16];
#pragma unroll
    for (int i = 0; i < 16; i++) acc[i] = 0.f;

    int mrow = wid * 16;
    int px_l = mrow + (lane & 15);
    int ly_l = px_l >> 4, lx_l = px_l & 15;
    u32 a_chunk = (u32)(lane >> 4) * 16u;
    u32 b_off = (u32)((lane & 7) + ((lane >> 4) << 3)) * STRIDE_B
              + (u32)((lane >> 3) & 1) * 16u;

#pragma unroll 1
    for (int t9 = 0; t9 < 9; t9++) {
        int kh = t9 / 3, kw = t9 - kh * 3;
        if (t9 < 8) cp_bA(Bbase + (u32)(((t9 + 1) & 1) * CA_B_BYTES), t9 + 1, tid);
        u32 Bcur = Bbase + (u32)((t9 & 1) * CA_B_BYTES);
        u32 a_base = (u32)((ly_l + kh) * 18 + lx_l + kw) * STRIDE_B + a_chunk;

#pragma unroll 1
        for (int kk = 0; kk < 8; kk++) {
            u32 koff = (u32)kk * 32u;
            u32 a[4], b0[4], b1[4];
            ldm4(Sb + a_base + koff, a);
            ldm4(Bcur + b_off + koff, b0);
            ldm4(Bcur + b_off + 16u * STRIDE_B + koff, b1);
            mma16816f(acc + 0,  a, b0[0], b0[1]);
            mma16816f(acc + 4,  a, b0[2], b0[3]);
            mma16816f(acc + 8,  a, b1[0], b1[1]);
            mma16816f(acc + 12, a, b1[2], b1[3]);
        }
        if (t9 < 8) {
            asm volatile("cp.async.wait_group 0;" ::: "memory");
            __syncthreads();
        }
    }
    __syncthreads();

    // epilogue 1: frags -> dsm[px][33]
    float* dsm = (float*)smc;
    {
        int g = lane >> 2, t = lane & 3;
#pragma unroll
        for (int si = 0; si < 4; si++) {
            int ob = si * 8;
            dsm[(mrow + g)     * 33 + ob + 2 * t]     = acc[si * 4 + 0];
            dsm[(mrow + g)     * 33 + ob + 2 * t + 1] = acc[si * 4 + 1];
            dsm[(mrow + g + 8) * 33 + ob + 2 * t]     = acc[si * 4 + 2];
            dsm[(mrow + g + 8) * 33 + ob + 2 * t + 1] = acc[si * 4 + 3];
        }
    }
    __syncthreads();

    // epilogue 2: bias + sigmoid + bilinear meta -> g_meta
    for (int idx = tid; idx < 128 * 9; idx += 256) {
        int px = idx / 9, n = idx - px * 9;
        float offx = dsm[px * 33 + n]      + b_p[n];
        float offy = dsm[px * 33 + 9 + n]  + b_p[9 + n];
        float mval = 1.f / (1.f + expf(-(dsm[px * 33 + 18 + n] + b_m[n])));
        int h = h0 + (px >> 4), w = w0 + (px & 15);
        int iI = n / 3, jJ = n - iI * 3;
        float p_x = offx + (float)(iI - 1) + (float)(h + 1);
        float p_y = offy + (float)(jJ - 1) + (float)(w + 1);
        float flx = floorf(p_x), fly = floorf(p_y);
        float ltx = fminf(fmaxf(flx, 0.f), 129.f);
        float lty = fminf(fmaxf(fly, 0.f), 129.f);
        float rbx = fminf(fmaxf(flx + 1.f, 0.f), 129.f);
        float rby = fminf(fmaxf(fly + 1.f, 0.f), 129.f);
        float cpx = fminf(fmaxf(p_x, 0.f), 129.f);
        float cpy = fminf(fmaxf(p_y, 0.f), 129.f);
        float ax  = 1.f + (ltx - cpx);
        float bx_ = 1.f - (rbx - cpx);
        float ay  = 1.f + (lty - cpy);
        float by_ = 1.f - (rby - cpy);
        float wq[4] = { ax * ay * mval, bx_ * by_ * mval, ax * by_ * mval, bx_ * ay * mval };
        float qxf[4] = { ltx, rbx, ltx, rbx };
        float qyf[4] = { lty, rby, rby, lty };
        int4 bs;
        int* bsp = &bs.x;
#pragma unroll
        for (int j = 0; j < 4; j++) {
            int ix = (int)qxf[j], iy = (int)qyf[j];
            bool valid = (ix >= 1 && ix <= Hh && iy >= 1 && iy <= Ww);
            bsp[j] = valid ? (((b * Hh + ix - 1) * Ww + iy - 1) * 32) : 0;
            if (!valid) wq[j] = 0.f;
        }
        int4* mp = (int4*)&g_meta[(((b * Hh + h) * Ww + w) * 9 + n) * 8];
        mp[0] = bs;
        ((float4*)mp)[1] = make_float4(wq[0], wq[1], wq[2], wq[3]);
    }
}

// ---------------------------------------------------------------
// Deform gather (meta-driven, fp16): one conv-tap k for a 64-px tile.
// 16 warps x 4 px; lanes cover 128 channels as uint2 (4 fp16).
__device__ __forceinline__ void gather_tapD(int b, int k, int oh0, int ow0,
                                            int lane, int wid, char* Adst) {
    const uint2* xt2 = (const uint2*)g_xt;
    int di = k / 3, dj = k - di * 3;
    int dh = (di == 0) ? -1 : 0;
    int iI = (di == 0) ? 2 : (di == 1 ? 0 : 1);
    int dw = (dj == 0) ? -1 : 0;
    int jJ = (dj == 0) ? 2 : (dj == 1 ? 0 : 1);
    int n = iI * 3 + jJ;
#pragma unroll
    for (int s = 0; s < 4; s++) {
        int px = wid * 4 + s;
        int ly = px >> 4, lx = px & 15;
        int h = oh0 + ly + dh, w = ow0 + lx + dw;
        float4 sv = make_float4(0.f, 0.f, 0.f, 0.f);
        if (h >= 0 && w >= 0) {
            const int4* mp = (const int4*)&g_meta[(((b * Hh + h) * Ww + w) * 9 + n) * 8];
            int4   bs = __ldg(mp);
            float4 wf = __ldg((const float4*)mp + 1);
            const int* bsp = &bs.x;
            const float* wfp = &wf.x;
#pragma unroll
            for (int j = 0; j < 4; j++) {
                uint2 q = xt2[bsp[j] + lane];
                float wj = wfp[j];
                float2 f0 = __half22float2(*(__half2*)&q.x);
                float2 f1 = __half22float2(*(__half2*)&q.y);
                sv.x = fmaf(wj, f0.x, sv.x);
                sv.y = fmaf(wj, f0.y, sv.y);
                sv.z = fmaf(wj, f1.x, sv.z);
                sv.w = fmaf(wj, f1.y, sv.w);
            }
        }
        __half2 o0 = __floats2half2_rn(sv.x, sv.y);
        __half2 o1 = __floats2half2_rn(sv.z, sv.w);
        *(uint2*)(Adst + px * STRIDE_B + lane * 8) = make_uint2(*(u32*)&o0, *(u32*)&o1);
    }
}

// Deform MMA for one tap: warp = 16px x 32o, fp16 single term.
__device__ __forceinline__ void mma_tapD(u32 Acur, u32 Bcur, u32 a_off, u32 b_off,
                                         float* acc) {
#pragma unroll 1
    for (int kk = 0; kk < 8; kk++) {
        u32 koff = (u32)kk * 32u;
        u32 a[4], b0[4], b1[4];
        ldm4(Acur + a_off + koff, a);
        ldm4(Bcur + b_off + koff, b0);
        ldm4(Bcur + b_off + 16u * STRIDE_B + koff, b1);
        mma16816f(acc + 0,  a, b0[0], b0[1]);
        mma16816f(acc + 4,  a, b0[2], b0[3]);
        mma16816f(acc + 8,  a, b1[0], b1[1]);
        mma16816f(acc + 12, a, b1[2], b1[3]);
    }
}

// ---------------------------------------------------------------
// Kernel B: meta-driven deformable gather -> fp16 mma.sync GEMM, double-buffered.
// Block 512 / 16 warps; tile M=64 px (4h x 16w) x N=128 o; 2 CTAs/SM.
// Per tap: odd warps gather(k+1) then MMA(k); even warps MMA(k) then gather(k+1).
__global__ void __launch_bounds__(512, 2) k_deform(float* __restrict__ out) {
    extern __shared__ char smc[];
    u32 Sb = smem_u32(smc);
    u32 Bbase = Sb + 2 * D_A_BYTES;

    int b   = blockIdx.z;
    int oh0 = blockIdx.y * 4, ow0 = blockIdx.x * 16;
    int tid  = threadIdx.x;
    int lane = tid & 31, wid = tid >> 5;
    int mrow = (wid & 3) * 16;
    int nb   = (wid >> 2) * 32;

    float acc[16];
#pragma unroll
    for (int i = 0; i < 16; i++) acc[i] = 0.f;

    u32 a_off = (u32)(mrow + (lane & 15)) * STRIDE_B + (u32)(lane >> 4) * 16u;
    u32 b_off = (u32)(nb + (lane & 7) + ((lane >> 4) << 3)) * STRIDE_B
              + (u32)((lane >> 3) & 1) * 16u;

    // prologue: tap 0 into A0/B0
    cp_bD(Bbase, 0, tid);
    gather_tapD(b, 0, oh0, ow0, lane, wid, smc);
    asm volatile("cp.async.wait_group 0;" ::: "memory");
    __syncthreads();

#pragma unroll 1
    for (int k = 0; k < 9; k++) {
        int cur = k & 1;
        u32 Acur = Sb + (u32)cur * D_A_BYTES;
        u32 Bcur = Bbase + (u32)cur * D_B_BYTES;
        char* Anxt = smc + (cur ^ 1) * D_A_BYTES;

        if (k < 8) cp_bD(Bbase + (u32)(cur ^ 1) * D_B_BYTES, k + 1, tid);

        if (wid & 1) {
            if (k < 8) gather_tapD(b, k + 1, oh0, ow0, lane, wid, Anxt);
            mma_tapD(Acur, Bcur, a_off, b_off, acc);
        } else {
            mma_tapD(Acur, Bcur, a_off, b_off, acc);
            if (k < 8) gather_tapD(b, k + 1, oh0, ow0, lane, wid, Anxt);
        }
        if (k < 8) asm volatile("cp.async.wait_group 0;" ::: "memory");
        __syncthreads();
    }

    // epilogue: direct global stores
    {
        int g = lane >> 2, t = lane & 3;
        int oh = oh0 + (mrow >> 4);
        int ow1 = ow0 + g, ow2 = ow0 + g + 8;
#pragma unroll
        for (int si = 0; si < 4; si++) {
            int o0 = nb + si * 8 + 2 * t;
            float* r0 = &out[((b * OC + o0) * Hh + oh) * Ww];
            float* r1 = &out[((b * OC + o0 + 1) * Hh + oh) * Ww];
            r0[ow1] = acc[si * 4 + 0];
            r1[ow1] = acc[si * 4 + 1];
            r0[ow2] = acc[si * 4 + 2];
            r1[ow2] = acc[si * 4 + 3];
        }
    }
}

// ---------------------------------------------------------------
extern "C" void kernel_launch(void* const* d_in, const int* in_sizes, int n_in,
                              void* d_out, int out_size) {
    const float* x      = (const float*)d_in[0];
    const float* w_p    = (const float*)d_in[1];
    const float* b_p    = (const float*)d_in[2];
    const float* w_m    = (const float*)d_in[3];
    const float* b_m    = (const float*)d_in[4];
    const float* w_conv = (const float*)d_in[5];
    float* out = (float*)d_out;

    cudaFuncSetAttribute(k_convA,  cudaFuncAttributeMaxDynamicSharedMemorySize, CA_SMEM);
    cudaFuncSetAttribute(k_deform, cudaFuncAttributeMaxDynamicSharedMemorySize, D_SMEM);

    k_transpose_x<<<dim3(4, 4, Bn * Hh), dim3(32, 8)>>>(x);

    int wthreads = 9 * 128 * 128 + 9 * 27 * 128;
    k_transpose_w<<<(wthreads + 255) / 256, 256>>>(w_conv, w_p, w_m);

    // convA: tile 8(h) x 16(w): grid (8, 16, B) = 256 CTAs
    k_convA<<<dim3(8, 16, Bn), 256, CA_SMEM>>>(b_p, b_m);

    // deform: tile 4(h) x 16(w): grid (8, 32, B) = 512 CTAs
    k_deform<<<dim3(8, 32, Bn), 512, D_SMEM>>>(out);
}

// round 12
// speedup vs baseline: 2.3307x; 1.0820x over previous
#include <cuda_runtime.h>
#include <cuda_fp16.h>
#include <math.h>

// Problem constants: B=2, C=128, H=W=128, outc=128, KS=3, N=9, PAD=1
#define Bn 2
#define Cn 128
#define Hh 128
#define Ww 128
#define OC 128

typedef unsigned long long u64;
typedef unsigned int u32;

// -------- scratch (static device globals; no allocation allowed) --------
__device__ __half g_xt [Bn*Hh*Ww*Cn];              // x as fp16 [B,H,W,C]
// per (b,h,w,n) gather meta (32B): {int4 corner byte-offsets, half2 w01, half2 w23, 8B pad}
__device__ __align__(16) int g_meta[Bn*Hh*Ww*9*8]; // 9.4 MB
__device__ __align__(16) __half g_wd[9*128*136];   // deform W fp16 [k][o][c], row stride 136
__device__ __align__(16) __half g_wa[9*32*136];    // convA W fp16 [k][o(27)][c]; rows 27-31 zero

#define STRIDE_B 272                 // 136 fp16 per row
#define D_A_BYTES 17408              // 64 rows
#define D_B_BYTES 34816              // 128 rows
#define D_SMEM (2*17408 + 2*34816)   // 104448  (A0 A1 B0 B1)

#define CA_HALO_BYTES (180*272)      // 48960 (10h x 18w halo rows)
#define CA_B_BYTES 8704              // 32 rows
#define CA_SMEM (48960 + 2*8704)     // 66368

__device__ __forceinline__ u32 smem_u32(const void* p) {
    u32 a;
    asm("{ .reg .u64 t; cvta.to.shared.u64 t, %1; cvt.u32.u64 %0, t; }" : "=r"(a) : "l"(p));
    return a;
}

__device__ __forceinline__ void ldm4(u32 addr, u32* r) {
    asm volatile("ldmatrix.sync.aligned.m8n8.x4.shared.b16 {%0,%1,%2,%3}, [%4];"
                 : "=r"(r[0]), "=r"(r[1]), "=r"(r[2]), "=r"(r[3]) : "r"(addr));
}

__device__ __forceinline__ void mma16816f(float* c, const u32* a, u32 b0, u32 b1) {
    asm volatile("mma.sync.aligned.m16n8k16.row.col.f32.f16.f16.f32 "
                 "{%0,%1,%2,%3}, {%4,%5,%6,%7}, {%8,%9}, {%0,%1,%2,%3};"
                 : "+f"(c[0]), "+f"(c[1]), "+f"(c[2]), "+f"(c[3])
                 : "r"(a[0]), "r"(a[1]), "r"(a[2]), "r"(a[3]), "r"(b0), "r"(b1));
}

// ---------------------------------------------------------------
// Kernel 0a: transpose x NCHW -> BHWC (fp16 output)
__global__ void k_transpose_x(const float* __restrict__ x) {
    __shared__ float tile[32][33];
    int bxw = blockIdx.x, byc = blockIdx.y, bz = blockIdx.z;
    int b = bz >> 7, h = bz & 127;
    int tx = threadIdx.x, ty = threadIdx.y;
#pragma unroll
    for (int i = 0; i < 4; i++) {
        int c = byc * 32 + ty + i * 8;
        tile[ty + i * 8][tx] = x[((b * Cn + c) * Hh + h) * Ww + bxw * 32 + tx];
    }
    __syncthreads();
#pragma unroll
    for (int i = 0; i < 4; i++) {
        int w = bxw * 32 + ty + i * 8;
        g_xt[((b * Hh + h) * Ww + w) * Cn + byc * 32 + tx] = __float2half(tile[tx][ty + i * 8]);
    }
}

// ---------------------------------------------------------------
// Kernel 0b: weight re-layouts (fp16 ldmatrix row images)
__global__ void k_transpose_w(const float* __restrict__ w_conv,
                              const float* __restrict__ w_p,
                              const float* __restrict__ w_m) {
    int t = blockIdx.x * blockDim.x + threadIdx.x;
    if (t < 9 * 128 * 128) {
        int c = t & 127;
        int o = (t >> 7) & 127;
        int k = t >> 14;
        int di = k / 3, dj = k - di * 3;
        float val = w_conv[((o * Cn + c) * 3 + di) * 3 + dj];
        g_wd[(k * 128 + o) * 136 + c] = __float2half(val);
    } else {
        int t2 = t - 9 * 128 * 128;
        if (t2 < 9 * 27 * 128) {
            int c = t2 & 127;
            int rest = t2 >> 7;
            int o = rest % 27;
            int k = rest / 27;
            int kh = k / 3, kw = k - kh * 3;
            float val;
            if (o < 18) val = w_p[((o * Cn + c) * 3 + kh) * 3 + kw];
            else        val = w_m[(((o - 18) * Cn + c) * 3 + kh) * 3 + kw];
            g_wa[(k * 32 + o) * 136 + c] = __float2half(val);
        }
    }
}

// stage tap-k convA weights (8704 B = 544 x 16B) via cp.async (256 thr)
__device__ __forceinline__ void cp_bA(u32 dst, int k, int tid) {
    const char* src = (const char*)g_wa + k * CA_B_BYTES;
#pragma unroll
    for (int i = 0; i < 3; i++) {
        int idx = tid + i * 256;
        if (idx < 544) {
            asm volatile("cp.async.cg.shared.global [%0], [%1], 16;"
                         :: "r"(dst + (u32)idx * 16u), "l"(src + idx * 16) : "memory");
        }
    }
    asm volatile("cp.async.commit_group;" ::: "memory");
}

// stage tap-k deform weights (34816 B = 2176 x 16B) via cp.async (512 thr)
__device__ __forceinline__ void cp_bD(u32 dst, int k, int tid) {
    const char* src = (const char*)g_wd + k * D_B_BYTES;
#pragma unroll
    for (int i = 0; i < 5; i++) {
        int idx = tid + i * 512;
        if (idx < 2176) {
            asm volatile("cp.async.cg.shared.global [%0], [%1], 16;"
                         :: "r"(dst + (u32)idx * 16u), "l"(src + idx * 16) : "memory");
        }
    }
    asm volatile("cp.async.commit_group;" ::: "memory");
}

// ---------------------------------------------------------------
// Kernel A: fused offset(18)+mask(9) 3x3 conv (fp16 mma + smem halo),
// epilogue computes deformable-gather metadata per (px, n):
// 4 corner byte-offsets + 4 modulated bilinear weights (packed half2) -> g_meta.
__global__ void __launch_bounds__(256, 2) k_convA(const float* __restrict__ b_p,
                                                  const float* __restrict__ b_m) {
    extern __shared__ char smc[];
    u32 Sb = smem_u32(smc);
    u32 Bbase = Sb + CA_HALO_BYTES;

    int b  = blockIdx.z;
    int h0 = blockIdx.y * 8, w0 = blockIdx.x * 16;
    int tid = threadIdx.x;
    int lane = tid & 31, wid = tid >> 5;   // 8 warps

    cp_bA(Bbase, 0, tid);

    // halo copy: 180 rows, fp16 direct (lane -> 4 channels = 8B)
    const uint2* xt2 = (const uint2*)g_xt;
    for (int r = wid; r < 180; r += 8) {
        int hy = r / 18, hx = r - hy * 18;
        int h = h0 - 1 + hy, w = w0 - 1 + hx;
        uint2 v = make_uint2(0u, 0u);
        if (h >= 0 && h < Hh && w >= 0 && w < Ww)
            v = xt2[((b * Hh + h) * Ww + w) * 32 + lane];
        *(uint2*)(smc + r * STRIDE_B + lane * 8) = v;
    }
    asm volatile("cp.async.wait_group 0;" ::: "memory");
    __syncthreads();

    float acc[16];
#pragma unroll
    for (int i = 0; i < 16; i++) acc[i] = 0.f;

    int mrow = wid * 16;
    int px_l = mrow + (lane & 15);
    int ly_l = px_l >> 4, lx_l = px_l & 15;
    u32 a_chunk = (u32)(lane >> 4) * 16u;
    u32 b_off = (u32)((lane & 7) + ((lane >> 4) << 3)) * STRIDE_B
              + (u32)((lane >> 3) & 1) * 16u;

#pragma unroll 1
    for (int t9 = 0; t9 < 9; t9++) {
        int kh = t9 / 3, kw = t9 - kh * 3;
        if (t9 < 8) cp_bA(Bbase + (u32)(((t9 + 1) & 1) * CA_B_BYTES), t9 + 1, tid);
        u32 Bcur = Bbase + (u32)((t9 & 1) * CA_B_BYTES);
        u32 a_base = (u32)((ly_l + kh) * 18 + lx_l + kw) * STRIDE_B + a_chunk;

#pragma unroll 1
        for (int kk = 0; kk < 8; kk++) {
            u32 koff = (u32)kk * 32u;
            u32 a[4], b0[4], b1[4];
            ldm4(Sb + a_base + koff, a);
            ldm4(Bcur + b_off + koff, b0);
            ldm4(Bcur + b_off + 16u * STRIDE_B + koff, b1);
            mma16816f(acc + 0,  a, b0[0], b0[1]);
            mma16816f(acc + 4,  a, b0[2], b0[3]);
            mma16816f(acc + 8,  a, b1[0], b1[1]);
            mma16816f(acc + 12, a, b1[2], b1[3]);
        }
        if (t9 < 8) {
            asm volatile("cp.async.wait_group 0;" ::: "memory");
            __syncthreads();
        }
    }
    __syncthreads();

    // epilogue 1: frags -> dsm[px][33]
    float* dsm = (float*)smc;
    {
        int g = lane >> 2, t = lane & 3;
#pragma unroll
        for (int si = 0; si < 4; si++) {
            int ob = si * 8;
            dsm[(mrow + g)     * 33 + ob + 2 * t]     = acc[si * 4 + 0];
            dsm[(mrow + g)     * 33 + ob + 2 * t + 1] = acc[si * 4 + 1];
            dsm[(mrow + g + 8) * 33 + ob + 2 * t]     = acc[si * 4 + 2];
            dsm[(mrow + g + 8) * 33 + ob + 2 * t + 1] = acc[si * 4 + 3];
        }
    }
    __syncthreads();

    // epilogue 2: bias + sigmoid + bilinear meta -> g_meta
    for (int idx = tid; idx < 128 * 9; idx += 256) {
        int px = idx / 9, n = idx - px * 9;
        float offx = dsm[px * 33 + n]      + b_p[n];
        float offy = dsm[px * 33 + 9 + n]  + b_p[9 + n];
        float mval = 1.f / (1.f + expf(-(dsm[px * 33 + 18 + n] + b_m[n])));
        int h = h0 + (px >> 4), w = w0 + (px & 15);
        int iI = n / 3, jJ = n - iI * 3;
        float p_x = offx + (float)(iI - 1) + (float)(h + 1);
        float p_y = offy + (float)(jJ - 1) + (float)(w + 1);
        float flx = floorf(p_x), fly = floorf(p_y);
        float ltx = fminf(fmaxf(flx, 0.f), 129.f);
        float lty = fminf(fmaxf(fly, 0.f), 129.f);
        float rbx = fminf(fmaxf(flx + 1.f, 0.f), 129.f);
        float rby = fminf(fmaxf(fly + 1.f, 0.f), 129.f);
        float cpx = fminf(fmaxf(p_x, 0.f), 129.f);
        float cpy = fminf(fmaxf(p_y, 0.f), 129.f);
        float ax  = 1.f + (ltx - cpx);
        float bx_ = 1.f - (rbx - cpx);
        float ay  = 1.f + (lty - cpy);
        float by_ = 1.f - (rby - cpy);
        float wq[4] = { ax * ay * mval, bx_ * by_ * mval, ax * by_ * mval, bx_ * ay * mval };
        float qxf[4] = { ltx, rbx, ltx, rbx };
        float qyf[4] = { lty, rby, rby, lty };
        int4 bs;
        int* bsp = &bs.x;
#pragma unroll
        for (int j = 0; j < 4; j++) {
            int ix = (int)qxf[j], iy = (int)qyf[j];
            bool valid = (ix >= 1 && ix <= Hh && iy >= 1 && iy <= Ww);
            // corner base as BYTE offset into g_xt (128 ch * 2B = 256B per pixel)
            bsp[j] = valid ? (((b * Hh + ix - 1) * Ww + iy - 1) * 256) : 0;
            if (!valid) wq[j] = 0.f;
        }
        int4* mp = (int4*)&g_meta[(((b * Hh + h) * Ww + w) * 9 + n) * 8];
        mp[0] = bs;
        __half2 w01 = __floats2half2_rn(wq[0], wq[1]);
        __half2 w23 = __floats2half2_rn(wq[2], wq[3]);
        ((uint2*)mp)[2] = make_uint2(*(u32*)&w01, *(u32*)&w23);
    }
}

// ---------------------------------------------------------------
// Deform gather (meta-driven, packed half2 math): one conv-tap k, 64-px tile.
// 16 warps x 4 px; lanes cover 128 channels as uint2 (4 fp16).
// Per corner: 1 LDG.64 + 2 HFMA2 — no fp32 conversions.
__device__ __forceinline__ void gather_tapD(int b, int k, int oh0, int ow0,
                                            int lane, int wid, char* Adst) {
    const char* xb = (const char*)g_xt + lane * 8;
    int di = k / 3, dj = k - di * 3;
    int dh = (di == 0) ? -1 : 0;
    int iI = (di == 0) ? 2 : (di == 1 ? 0 : 1);
    int dw = (dj == 0) ? -1 : 0;
    int jJ = (dj == 0) ? 2 : (dj == 1 ? 0 : 1);
    int n = iI * 3 + jJ;
#pragma unroll
    for (int s = 0; s < 4; s++) {
        int px = wid * 4 + s;
        int ly = px >> 4, lx = px & 15;
        int h = oh0 + ly + dh, w = ow0 + lx + dw;
        __half2 a01 = __float2half2_rn(0.f), a23 = __float2half2_rn(0.f);
        if (h >= 0 && w >= 0) {
            const int4* mp = (const int4*)&g_meta[(((b * Hh + h) * Ww + w) * 9 + n) * 8];
            int4 bs = __ldg(mp);
            uint2 wp = __ldg((const uint2*)mp + 2);
            __half2 w01 = *(__half2*)&wp.x;
            __half2 w23 = *(__half2*)&wp.y;
            __half2 wb0 = __half2half2(__low2half(w01));
            __half2 wb1 = __half2half2(__high2half(w01));
            __half2 wb2 = __half2half2(__low2half(w23));
            __half2 wb3 = __half2half2(__high2half(w23));
            uint2 q0 = *(const uint2*)(xb + bs.x);
            uint2 q1 = *(const uint2*)(xb + bs.y);
            uint2 q2 = *(const uint2*)(xb + bs.z);
            uint2 q3 = *(const uint2*)(xb + bs.w);
            a01 = __hfma2(wb0, *(__half2*)&q0.x, a01);
            a23 = __hfma2(wb0, *(__half2*)&q0.y, a23);
            a01 = __hfma2(wb1, *(__half2*)&q1.x, a01);
            a23 = __hfma2(wb1, *(__half2*)&q1.y, a23);
            a01 = __hfma2(wb2, *(__half2*)&q2.x, a01);
            a23 = __hfma2(wb2, *(__half2*)&q2.y, a23);
            a01 = __hfma2(wb3, *(__half2*)&q3.x, a01);
            a23 = __hfma2(wb3, *(__half2*)&q3.y, a23);
        }
        *(uint2*)(Adst + px * STRIDE_B + lane * 8) = make_uint2(*(u32*)&a01, *(u32*)&a23);
    }
}

// Deform MMA for one tap: warp = 16px x 32o, fp16 single term.
__device__ __forceinline__ void mma_tapD(u32 Acur, u32 Bcur, u32 a_off, u32 b_off,
                                         float* acc) {
#pragma unroll 1
    for (int kk = 0; kk < 8; kk++) {
        u32 koff = (u32)kk * 32u;
        u32 a[4], b0[4], b1[4];
        ldm4(Acur + a_off + koff, a);
        ldm4(Bcur + b_off + koff, b0);
        ldm4(Bcur + b_off + 16u * STRIDE_B + koff, b1);
        mma16816f(acc + 0,  a, b0[0], b0[1]);
        mma16816f(acc + 4,  a, b0[2], b0[3]);
        mma16816f(acc + 8,  a, b1[0], b1[1]);
        mma16816f(acc + 12, a, b1[2], b1[3]);
    }
}

// ---------------------------------------------------------------
// Kernel B: meta-driven deformable gather -> fp16 mma.sync GEMM, double-buffered.
// Block 512 / 16 warps; tile M=64 px (4h x 16w) x N=128 o; 2 CTAs/SM.
// Per tap: odd warps gather(k+1) then MMA(k); even warps MMA(k) then gather(k+1).
__global__ void __launch_bounds__(512, 2) k_deform(float* __restrict__ out) {
    extern __shared__ char smc[];
    u32 Sb = smem_u32(smc);
    u32 Bbase = Sb + 2 * D_A_BYTES;

    int b   = blockIdx.z;
    int oh0 = blockIdx.y * 4, ow0 = blockIdx.x * 16;
    int tid  = threadIdx.x;
    int lane = tid & 31, wid = tid >> 5;
    int mrow = (wid & 3) * 16;
    int nb   = (wid >> 2) * 32;

    float acc[16];
#pragma unroll
    for (int i = 0; i < 16; i++) acc[i] = 0.f;

    u32 a_off = (u32)(mrow + (lane & 15)) * STRIDE_B + (u32)(lane >> 4) * 16u;
    u32 b_off = (u32)(nb + (lane & 7) + ((lane >> 4) << 3)) * STRIDE_B
              + (u32)((lane >> 3) & 1) * 16u;

    // prologue: tap 0 into A0/B0
    cp_bD(Bbase, 0, tid);
    gather_tapD(b, 0, oh0, ow0, lane, wid, smc);
    asm volatile("cp.async.wait_group 0;" ::: "memory");
    __syncthreads();

#pragma unroll 1
    for (int k = 0; k < 9; k++) {
        int cur = k & 1;
        u32 Acur = Sb + (u32)cur * D_A_BYTES;
        u32 Bcur = Bbase + (u32)cur * D_B_BYTES;
        char* Anxt = smc + (cur ^ 1) * D_A_BYTES;

        if (k < 8) cp_bD(Bbase + (u32)(cur ^ 1) * D_B_BYTES, k + 1, tid);

        if (wid & 1) {
            if (k < 8) gather_tapD(b, k + 1, oh0, ow0, lane, wid, Anxt);
            mma_tapD(Acur, Bcur, a_off, b_off, acc);
        } else {
            mma_tapD(Acur, Bcur, a_off, b_off, acc);
            if (k < 8) gather_tapD(b, k + 1, oh0, ow0, lane, wid, Anxt);
        }
        if (k < 8) asm volatile("cp.async.wait_group 0;" ::: "memory");
        __syncthreads();
    }

    // epilogue: direct global stores
    {
        int g = lane >> 2, t = lane & 3;
        int oh = oh0 + (mrow >> 4);
        int ow1 = ow0 + g, ow2 = ow0 + g + 8;
#pragma unroll
        for (int si = 0; si < 4; si++) {
            int o0 = nb + si * 8 + 2 * t;
            float* r0 = &out[((b * OC + o0) * Hh + oh) * Ww];
            float* r1 = &out[((b * OC + o0 + 1) * Hh + oh) * Ww];
            r0[ow1] = acc[si * 4 + 0];
            r1[ow1] = acc[si * 4 + 1];
            r0[ow2] = acc[si * 4 + 2];
            r1[ow2] = acc[si * 4 + 3];
        }
    }
}

// ---------------------------------------------------------------
extern "C" void kernel_launch(void* const* d_in, const int* in_sizes, int n_in,
                              void* d_out, int out_size) {
    const float* x      = (const float*)d_in[0];
    const float* w_p    = (const float*)d_in[1];
    const float* b_p    = (const float*)d_in[2];
    const float* w_m    = (const float*)d_in[3];
    const float* b_m    = (const float*)d_in[4];
    const float* w_conv = (const float*)d_in[5];
    float* out = (float*)d_out;

    cudaFuncSetAttribute(k_convA,  cudaFuncAttributeMaxDynamicSharedMemorySize, CA_SMEM);
    cudaFuncSetAttribute(k_deform, cudaFuncAttributeMaxDynamicSharedMemorySize, D_SMEM);

    k_transpose_x<<<dim3(4, 4, Bn * Hh), dim3(32, 8)>>>(x);

    int wthreads = 9 * 128 * 128 + 9 * 27 * 128;
    k_transpose_w<<<(wthreads + 255) / 256, 256>>>(w_conv, w_p, w_m);

    // convA: tile 8(h) x 16(w): grid (8, 16, B) = 256 CTAs
    k_convA<<<dim3(8, 16, Bn), 256, CA_SMEM>>>(b_p, b_m);

    // deform: tile 4(h) x 16(w): grid (8, 32, B) = 512 CTAs
    k_deform<<<dim3(8, 32, Bn), 512, D_SMEM>>>(out);
}

// round 13
// speedup vs baseline: 2.3792x; 1.0208x over previous
#include <cuda_runtime.h>
#include <cuda_fp16.h>
#include <math.h>

// Problem constants: B=2, C=128, H=W=128, outc=128, KS=3, N=9, PAD=1
#define Bn 2
#define Cn 128
#define Hh 128
#define Ww 128
#define OC 128

typedef unsigned long long u64;
typedef unsigned int u32;

// -------- scratch (static device globals; no allocation allowed) --------
__device__ __half g_xt [Bn*Hh*Ww*Cn];              // x as fp16 [B,H,W,C]
// per (b,h,w,n) gather meta (32B): {int4 corner byte-offsets, half2 w01, half2 w23, 8B pad}
__device__ __align__(16) int g_meta[Bn*Hh*Ww*9*8]; // 9.4 MB
// deform W pre-swizzled into mma.sync B-fragment order:
// uint4 index ((k*4+kk2)*16+ob)*32+lane ; .x/.y = kk even regs, .z/.w = kk odd
__device__ __align__(16) uint4 g_wd2[9*2048];      // 288 KB
__device__ __align__(16) __half g_wa[9*32*136];    // convA W fp16 [k][o(27)][c]; rows 27-31 zero

#define STRIDE_B 272                 // 136 fp16 per row
#define D_A_BYTES 17408              // 64 rows
#define D_SMEM (2*17408)             // 34816  (A0 A1 only; B streams via LDG)

#define CA_HALO_BYTES (180*272)      // 48960 (10h x 18w halo rows)
#define CA_B_BYTES 8704              // 32 rows
#define CA_SMEM (48960 + 2*8704)     // 66368

__device__ __forceinline__ u32 smem_u32(const void* p) {
    u32 a;
    asm("{ .reg .u64 t; cvta.to.shared.u64 t, %1; cvt.u32.u64 %0, t; }" : "=r"(a) : "l"(p));
    return a;
}

__device__ __forceinline__ void ldm4(u32 addr, u32* r) {
    asm volatile("ldmatrix.sync.aligned.m8n8.x4.shared.b16 {%0,%1,%2,%3}, [%4];"
                 : "=r"(r[0]), "=r"(r[1]), "=r"(r[2]), "=r"(r[3]) : "r"(addr));
}

__device__ __forceinline__ void mma16816f(float* c, const u32* a, u32 b0, u32 b1) {
    asm volatile("mma.sync.aligned.m16n8k16.row.col.f32.f16.f16.f32 "
                 "{%0,%1,%2,%3}, {%4,%5,%6,%7}, {%8,%9}, {%0,%1,%2,%3};"
                 : "+f"(c[0]), "+f"(c[1]), "+f"(c[2]), "+f"(c[3])
                 : "r"(a[0]), "r"(a[1]), "r"(a[2]), "r"(a[3]), "r"(b0), "r"(b1));
}

// ---------------------------------------------------------------
// Kernel 0a: transpose x NCHW -> BHWC (fp16, vectorized uint2 stores)
__global__ void k_transpose_x(const float* __restrict__ x) {
    __shared__ float tile[32][33];
    int bxw = blockIdx.x, byc = blockIdx.y, bz = blockIdx.z;
    int b = bz >> 7, h = bz & 127;
    int tx = threadIdx.x, ty = threadIdx.y;
    int t = ty * 32 + tx;
#pragma unroll
    for (int i = 0; i < 4; i++) {
        int c = byc * 32 + ty + i * 8;
        tile[ty + i * 8][tx] = x[((b * Cn + c) * Hh + h) * Ww + bxw * 32 + tx];
    }
    __syncthreads();
    // thread t: w_loc = t>>3 (0..31), c group = (t&7)*4
    {
        int w_loc = t >> 3, c_loc = (t & 7) * 4;
        __half2 p0 = __floats2half2_rn(tile[c_loc + 0][w_loc], tile[c_loc + 1][w_loc]);
        __half2 p1 = __floats2half2_rn(tile[c_loc + 2][w_loc], tile[c_loc + 3][w_loc]);
        u32 base = ((b * Hh + h) * Ww + bxw * 32 + w_loc) * Cn + byc * 32 + c_loc;
        *(uint2*)&g_xt[base] = make_uint2(*(u32*)&p0, *(u32*)&p1);
    }
}

// ---------------------------------------------------------------
// Kernel 0b: weight re-layouts.
// Range 1: w_conv -> g_wd2 (mma.sync B-fragment blob, fp16).
// Range 2: w_p/w_m -> g_wa (row image for convA's ldmatrix path).
__global__ void k_transpose_w(const float* __restrict__ w_conv,
                              const float* __restrict__ w_p,
                              const float* __restrict__ w_m) {
    int t = blockIdx.x * blockDim.x + threadIdx.x;
    if (t < 9 * 4 * 16 * 32) {
        int l   = t & 31;
        int ob  = (t >> 5) & 15;
        int kk2 = (t >> 9) & 3;
        int k   = t >> 11;           // tap 0..8
        int o   = ob * 8 + (l >> 2);
        int cb  = (l & 3) * 2;
        int di = k / 3, dj = k - di * 3;
        __half hv[8];
#pragma unroll
        for (int q = 0; q < 2; q++) {
            int c0 = (kk2 * 2 + q) * 16 + cb;
            hv[q * 4 + 0] = __float2half(w_conv[((o * Cn + c0)     * 3 + di) * 3 + dj]);
            hv[q * 4 + 1] = __float2half(w_conv[((o * Cn + c0 + 1) * 3 + di) * 3 + dj]);
            hv[q * 4 + 2] = __float2half(w_conv[((o * Cn + c0 + 8) * 3 + di) * 3 + dj]);
            hv[q * 4 + 3] = __float2half(w_conv[((o * Cn + c0 + 9) * 3 + di) * 3 + dj]);
        }
        uint4 v;
        v.x = *(u32*)&hv[0]; v.y = *(u32*)&hv[2];
        v.z = *(u32*)&hv[4]; v.w = *(u32*)&hv[6];
        g_wd2[((k * 4 + kk2) * 16 + ob) * 32 + l] = v;
    } else {
        int t2 = t - 9 * 4 * 16 * 32;
        if (t2 < 9 * 27 * 128) {
            int c = t2 & 127;
            int rest = t2 >> 7;
            int o = rest % 27;
            int k = rest / 27;
            int kh = k / 3, kw = k - kh * 3;
            float val;
            if (o < 18) val = w_p[((o * Cn + c) * 3 + kh) * 3 + kw];
            else        val = w_m[(((o - 18) * Cn + c) * 3 + kh) * 3 + kw];
            g_wa[(k * 32 + o) * 136 + c] = __float2half(val);
        }
    }
}

// stage tap-k convA weights (8704 B = 544 x 16B) via cp.async (256 thr)
__device__ __forceinline__ void cp_bA(u32 dst, int k, int tid) {
    const char* src = (const char*)g_wa + k * CA_B_BYTES;
#pragma unroll
    for (int i = 0; i < 3; i++) {
        int idx = tid + i * 256;
        if (idx < 544) {
            asm volatile("cp.async.cg.shared.global [%0], [%1], 16;"
                         :: "r"(dst + (u32)idx * 16u), "l"(src + idx * 16) : "memory");
        }
    }
    asm volatile("cp.async.commit_group;" ::: "memory");
}

// ---------------------------------------------------------------
// Kernel A: fused offset(18)+mask(9) 3x3 conv (fp16 mma + smem halo),
// epilogue emits deformable-gather metadata per (px, n).
__global__ void __launch_bounds__(256, 2) k_convA(const float* __restrict__ b_p,
                                                  const float* __restrict__ b_m) {
    extern __shared__ char smc[];
    u32 Sb = smem_u32(smc);
    u32 Bbase = Sb + CA_HALO_BYTES;

    int b  = blockIdx.z;
    int h0 = blockIdx.y * 8, w0 = blockIdx.x * 16;
    int tid = threadIdx.x;
    int lane = tid & 31, wid = tid >> 5;   // 8 warps

    cp_bA(Bbase, 0, tid);

    // halo copy: 180 rows, fp16 direct (lane -> 4 channels = 8B)
    const uint2* xt2 = (const uint2*)g_xt;
    for (int r = wid; r < 180; r += 8) {
        int hy = r / 18, hx = r - hy * 18;
        int h = h0 - 1 + hy, w = w0 - 1 + hx;
        uint2 v = make_uint2(0u, 0u);
        if (h >= 0 && h < Hh && w >= 0 && w < Ww)
            v = xt2[((b * Hh + h) * Ww + w) * 32 + lane];
        *(uint2*)(smc + r * STRIDE_B + lane * 8) = v;
    }
    asm volatile("cp.async.wait_group 0;" ::: "memory");
    __syncthreads();

    float acc[16];
#pragma unroll
    for (int i = 0; i < 16; i++) acc[i] = 0.f;

    int mrow = wid * 16;
    int px_l = mrow + (lane & 15);
    int ly_l = px_l >> 4, lx_l = px_l & 15;
    u32 a_chunk = (u32)(lane >> 4) * 16u;
    u32 b_off = (u32)((lane & 7) + ((lane >> 4) << 3)) * STRIDE_B
              + (u32)((lane >> 3) & 1) * 16u;

#pragma unroll 1
    for (int t9 = 0; t9 < 9; t9++) {
        int kh = t9 / 3, kw = t9 - kh * 3;
        if (t9 < 8) cp_bA(Bbase + (u32)(((t9 + 1) & 1) * CA_B_BYTES), t9 + 1, tid);
        u32 Bcur = Bbase + (u32)((t9 & 1) * CA_B_BYTES);
        u32 a_base = (u32)((ly_l + kh) * 18 + lx_l + kw) * STRIDE_B + a_chunk;

#pragma unroll 1
        for (int kk = 0; kk < 8; kk++) {
            u32 koff = (u32)kk * 32u;
            u32 a[4], b0[4], b1[4];
            ldm4(Sb + a_base + koff, a);
            ldm4(Bcur + b_off + koff, b0);
            ldm4(Bcur + b_off + 16u * STRIDE_B + koff, b1);
            mma16816f(acc + 0,  a, b0[0], b0[1]);
            mma16816f(acc + 4,  a, b0[2], b0[3]);
            mma16816f(acc + 8,  a, b1[0], b1[1]);
            mma16816f(acc + 12, a, b1[2], b1[3]);
        }
        if (t9 < 8) {
            asm volatile("cp.async.wait_group 0;" ::: "memory");
            __syncthreads();
        }
    }
    __syncthreads();

    // epilogue 1: frags -> dsm[px][33]
    float* dsm = (float*)smc;
    {
        int g = lane >> 2, t = lane & 3;
#pragma unroll
        for (int si = 0; si < 4; si++) {
            int ob = si * 8;
            dsm[(mrow + g)     * 33 + ob + 2 * t]     = acc[si * 4 + 0];
            dsm[(mrow + g)     * 33 + ob + 2 * t + 1] = acc[si * 4 + 1];
            dsm[(mrow + g + 8) * 33 + ob + 2 * t]     = acc[si * 4 + 2];
            dsm[(mrow + g + 8) * 33 + ob + 2 * t + 1] = acc[si * 4 + 3];
        }
    }
    __syncthreads();

    // epilogue 2: bias + sigmoid + bilinear meta -> g_meta
    for (int idx = tid; idx < 128 * 9; idx += 256) {
        int px = idx / 9, n = idx - px * 9;
        float offx = dsm[px * 33 + n]      + b_p[n];
        float offy = dsm[px * 33 + 9 + n]  + b_p[9 + n];
        float mval = 1.f / (1.f + expf(-(dsm[px * 33 + 18 + n] + b_m[n])));
        int h = h0 + (px >> 4), w = w0 + (px & 15);
        int iI = n / 3, jJ = n - iI * 3;
        float p_x = offx + (float)(iI - 1) + (float)(h + 1);
        float p_y = offy + (float)(jJ - 1) + (float)(w + 1);
        float flx = floorf(p_x), fly = floorf(p_y);
        float ltx = fminf(fmaxf(flx, 0.f), 129.f);
        float lty = fminf(fmaxf(fly, 0.f), 129.f);
        float rbx = fminf(fmaxf(flx + 1.f, 0.f), 129.f);
        float rby = fminf(fmaxf(fly + 1.f, 0.f), 129.f);
        float cpx = fminf(fmaxf(p_x, 0.f), 129.f);
        float cpy = fminf(fmaxf(p_y, 0.f), 129.f);
        float ax  = 1.f + (ltx - cpx);
        float bx_ = 1.f - (rbx - cpx);
        float ay  = 1.f + (lty - cpy);
        float by_ = 1.f - (rby - cpy);
        float wq[4] = { ax * ay * mval, bx_ * by_ * mval, ax * by_ * mval, bx_ * ay * mval };
        float qxf[4] = { ltx, rbx, ltx, rbx };
        float qyf[4] = { lty, rby, rby, lty };
        int4 bs;
        int* bsp = &bs.x;
#pragma unroll
        for (int j = 0; j < 4; j++) {
            int ix = (int)qxf[j], iy = (int)qyf[j];
            bool valid = (ix >= 1 && ix <= Hh && iy >= 1 && iy <= Ww);
            bsp[j] = valid ? (((b * Hh + ix - 1) * Ww + iy - 1) * 256) : 0;
            if (!valid) wq[j] = 0.f;
        }
        int4* mp = (int4*)&g_meta[(((b * Hh + h) * Ww + w) * 9 + n) * 8];
        mp[0] = bs;
        __half2 w01 = __floats2half2_rn(wq[0], wq[1]);
        __half2 w23 = __floats2half2_rn(wq[2], wq[3]);
        ((uint2*)mp)[2] = make_uint2(*(u32*)&w01, *(u32*)&w23);
    }
}

// ---------------------------------------------------------------
// Deform gather (meta-driven, packed half2): one conv-tap k, 64-px tile.
__device__ __forceinline__ void gather_tapD(int b, int k, int oh0, int ow0,
                                            int lane, int wid, char* Adst) {
    const char* xb = (const char*)g_xt + lane * 8;
    int di = k / 3, dj = k - di * 3;
    int dh = (di == 0) ? -1 : 0;
    int iI = (di == 0) ? 2 : (di == 1 ? 0 : 1);
    int dw = (dj == 0) ? -1 : 0;
    int jJ = (dj == 0) ? 2 : (dj == 1 ? 0 : 1);
    int n = iI * 3 + jJ;
#pragma unroll
    for (int s = 0; s < 4; s++) {
        int px = wid * 4 + s;
        int ly = px >> 4, lx = px & 15;
        int h = oh0 + ly + dh, w = ow0 + lx + dw;
        __half2 a01 = __float2half2_rn(0.f), a23 = __float2half2_rn(0.f);
        if (h >= 0 && w >= 0) {
            const int4* mp = (const int4*)&g_meta[(((b * Hh + h) * Ww + w) * 9 + n) * 8];
            int4 bs = __ldg(mp);
            uint2 wp = __ldg((const uint2*)mp + 2);
            __half2 w01 = *(__half2*)&wp.x;
            __half2 w23 = *(__half2*)&wp.y;
            __half2 wb0 = __half2half2(__low2half(w01));
            __half2 wb1 = __half2half2(__high2half(w01));
            __half2 wb2 = __half2half2(__low2half(w23));
            __half2 wb3 = __half2half2(__high2half(w23));
            uint2 q0 = *(const uint2*)(xb + bs.x);
            uint2 q1 = *(const uint2*)(xb + bs.y);
            uint2 q2 = *(const uint2*)(xb + bs.z);
            uint2 q3 = *(const uint2*)(xb + bs.w);
            a01 = __hfma2(wb0, *(__half2*)&q0.x, a01);
            a23 = __hfma2(wb0, *(__half2*)&q0.y, a23);
            a01 = __hfma2(wb1, *(__half2*)&q1.x, a01);
            a23 = __hfma2(wb1, *(__half2*)&q1.y, a23);
            a01 = __hfma2(wb2, *(__half2*)&q2.x, a01);
            a23 = __hfma2(wb2, *(__half2*)&q2.y, a23);
            a01 = __hfma2(wb3, *(__half2*)&q3.x, a01);
            a23 = __hfma2(wb3, *(__half2*)&q3.y, a23);
        }
        *(uint2*)(Adst + px * STRIDE_B + lane * 8) = make_uint2(*(u32*)&a01, *(u32*)&a23);
    }
}

// Deform MMA for one tap: warp = 16px x 32o; A via ldmatrix, B via direct
// register-fragment LDG.128 from the pre-swizzled g_wd2 blob (L1-resident).
__device__ __forceinline__ void mma_tapD(u32 Acur, const uint4* __restrict__ Bp,
                                         u32 a_off, int ob0, int lane, float* acc) {
#pragma unroll 1
    for (int kk2 = 0; kk2 < 4; kk2++) {
        u32 koff = (u32)kk2 * 64u;
        u32 aE[4], aO[4];
        ldm4(Acur + a_off + koff, aE);
        ldm4(Acur + a_off + koff + 32u, aO);
        const uint4* bq = Bp + (kk2 * 16 + ob0) * 32 + lane;
        uint4 b0 = __ldg(bq);
        uint4 b1 = __ldg(bq + 32);
        uint4 b2 = __ldg(bq + 64);
        uint4 b3 = __ldg(bq + 96);
        mma16816f(acc + 0,  aE, b0.x, b0.y);
        mma16816f(acc + 4,  aE, b1.x, b1.y);
        mma16816f(acc + 8,  aE, b2.x, b2.y);
        mma16816f(acc + 12, aE, b3.x, b3.y);
        mma16816f(acc + 0,  aO, b0.z, b0.w);
        mma16816f(acc + 4,  aO, b1.z, b1.w);
        mma16816f(acc + 8,  aO, b2.z, b2.w);
        mma16816f(acc + 12, aO, b3.z, b3.w);
    }
}

// ---------------------------------------------------------------
// Kernel B: meta-driven deformable gather -> fp16 mma.sync GEMM.
// Block 512 / 16 warps; tile M=64 px (4h x 16w) x N=128 o; 2 CTAs/SM.
// A double-buffered in smem; B streamed from global fragment blob (no smem).
__global__ void __launch_bounds__(512, 2) k_deform(float* __restrict__ out) {
    extern __shared__ char smc[];
    u32 Sb = smem_u32(smc);

    int b   = blockIdx.z;
    int oh0 = blockIdx.y * 4, ow0 = blockIdx.x * 16;
    int tid  = threadIdx.x;
    int lane = tid & 31, wid = tid >> 5;
    int mrow = (wid & 3) * 16;
    int ob0  = (wid >> 2) * 4;      // o-block base (o = ob0*8)

    float acc[16];
#pragma unroll
    for (int i = 0; i < 16; i++) acc[i] = 0.f;

    u32 a_off = (u32)(mrow + (lane & 15)) * STRIDE_B + (u32)(lane >> 4) * 16u;

    // prologue: tap 0 into A0
    gather_tapD(b, 0, oh0, ow0, lane, wid, smc);
    __syncthreads();

#pragma unroll 1
    for (int k = 0; k < 9; k++) {
        int cur = k & 1;
        u32 Acur = Sb + (u32)cur * D_A_BYTES;
        char* Anxt = smc + (cur ^ 1) * D_A_BYTES;
        const uint4* Bp = g_wd2 + k * 2048;

        if (wid & 1) {
            if (k < 8) gather_tapD(b, k + 1, oh0, ow0, lane, wid, Anxt);
            mma_tapD(Acur, Bp, a_off, ob0, lane, acc);
        } else {
            mma_tapD(Acur, Bp, a_off, ob0, lane, acc);
            if (k < 8) gather_tapD(b, k + 1, oh0, ow0, lane, wid, Anxt);
        }
        __syncthreads();
    }

    // epilogue: direct global stores
    {
        int g = lane >> 2, t = lane & 3;
        int oh = oh0 + (mrow >> 4);
        int ow1 = ow0 + g, ow2 = ow0 + g + 8;
        int nb = ob0 * 8;
#pragma unroll
        for (int si = 0; si < 4; si++) {
            int o0 = nb + si * 8 + 2 * t;
            float* r0 = &out[((b * OC + o0) * Hh + oh) * Ww];
            float* r1 = &out[((b * OC + o0 + 1) * Hh + oh) * Ww];
            r0[ow1] = acc[si * 4 + 0];
            r1[ow1] = acc[si * 4 + 1];
            r0[ow2] = acc[si * 4 + 2];
            r1[ow2] = acc[si * 4 + 3];
        }
    }
}

// ---------------------------------------------------------------
extern "C" void kernel_launch(void* const* d_in, const int* in_sizes, int n_in,
                              void* d_out, int out_size) {
    const float* x      = (const float*)d_in[0];
    const float* w_p    = (const float*)d_in[1];
    const float* b_p    = (const float*)d_in[2];
    const float* w_m    = (const float*)d_in[3];
    const float* b_m    = (const float*)d_in[4];
    const float* w_conv = (const float*)d_in[5];
    float* out = (float*)d_out;

    cudaFuncSetAttribute(k_convA,  cudaFuncAttributeMaxDynamicSharedMemorySize, CA_SMEM);
    cudaFuncSetAttribute(k_deform, cudaFuncAttributeMaxDynamicSharedMemorySize, D_SMEM);

    k_transpose_x<<<dim3(4, 4, Bn * Hh), dim3(32, 8)>>>(x);

    int wthreads = 9 * 4 * 16 * 32 + 9 * 27 * 128;
    k_transpose_w<<<(wthreads + 255) / 256, 256>>>(w_conv, w_p, w_m);

    // convA: tile 8(h) x 16(w): grid (8, 16, B) = 256 CTAs
    k_convA<<<dim3(8, 16, Bn), 256, CA_SMEM>>>(b_p, b_m);

    // deform: tile 4(h) x 16(w): grid (8, 32, B) = 512 CTAs
    k_deform<<<dim3(8, 32, Bn), 512, D_SMEM>>>(out);
}

// round 14
// speedup vs baseline: 2.6501x; 1.1139x over previous
#include <cuda_runtime.h>
#include <cuda_fp16.h>
#include <math.h>

// Problem constants: B=2, C=128, H=W=128, outc=128, KS=3, N=9, PAD=1
#define Bn 2
#define Cn 128
#define Hh 128
#define Ww 128
#define OC 128

typedef unsigned long long u64;
typedef unsigned int u32;

// -------- scratch (static device globals; no allocation allowed) --------
__device__ __half g_xt [Bn*Hh*Ww*Cn];              // x as fp16 [B,H,W,C]
// per (b,h,w,n) gather meta (32B): {int4 corner byte-offsets, half2 w01, half2 w23, 8B pad}
__device__ __align__(16) int g_meta[Bn*Hh*Ww*9*8]; // 9.4 MB
// deform W pre-swizzled into mma.sync B-fragment order:
// uint4 index ((k*4+kk2)*16+ob)*32+lane ; .x/.y = kk even regs, .z/.w = kk odd
__device__ __align__(16) uint4 g_wd2[9*2048];      // 288 KB
__device__ __align__(16) __half g_wa[9*32*136];    // convA W fp16 [k][o(27)][c]; rows 27-31 zero

#define STRIDE_B 272                 // 136 fp16 per row
#define D_A_BYTES 17408              // 64 rows
#define D_META_OFF (2*17408)         // meta after A0/A1
#define D_SMEM (2*17408 + 576*32)    // 53248

#define CA_HALO_BYTES (180*272)      // 48960 (10h x 18w halo rows)
#define CA_B_BYTES 8704              // 32 rows
#define CA_SMEM (48960 + 2*8704)     // 66368

__device__ __forceinline__ u32 smem_u32(const void* p) {
    u32 a;
    asm("{ .reg .u64 t; cvta.to.shared.u64 t, %1; cvt.u32.u64 %0, t; }" : "=r"(a) : "l"(p));
    return a;
}

__device__ __forceinline__ void ldm4(u32 addr, u32* r) {
    asm volatile("ldmatrix.sync.aligned.m8n8.x4.shared.b16 {%0,%1,%2,%3}, [%4];"
                 : "=r"(r[0]), "=r"(r[1]), "=r"(r[2]), "=r"(r[3]) : "r"(addr));
}

__device__ __forceinline__ void mma16816f(float* c, const u32* a, u32 b0, u32 b1) {
    asm volatile("mma.sync.aligned.m16n8k16.row.col.f32.f16.f16.f32 "
                 "{%0,%1,%2,%3}, {%4,%5,%6,%7}, {%8,%9}, {%0,%1,%2,%3};"
                 : "+f"(c[0]), "+f"(c[1]), "+f"(c[2]), "+f"(c[3])
                 : "r"(a[0]), "r"(a[1]), "r"(a[2]), "r"(a[3]), "r"(b0), "r"(b1));
}

// ---------------------------------------------------------------
// Kernel 0a: transpose x NCHW -> BHWC (fp16, vectorized uint2 stores)
__global__ void k_transpose_x(const float* __restrict__ x) {
    __shared__ float tile[32][33];
    int bxw = blockIdx.x, byc = blockIdx.y, bz = blockIdx.z;
    int b = bz >> 7, h = bz & 127;
    int tx = threadIdx.x, ty = threadIdx.y;
    int t = ty * 32 + tx;
#pragma unroll
    for (int i = 0; i < 4; i++) {
        int c = byc * 32 + ty + i * 8;
        tile[ty + i * 8][tx] = x[((b * Cn + c) * Hh + h) * Ww + bxw * 32 + tx];
    }
    __syncthreads();
    {
        int w_loc = t >> 3, c_loc = (t & 7) * 4;
        __half2 p0 = __floats2half2_rn(tile[c_loc + 0][w_loc], tile[c_loc + 1][w_loc]);
        __half2 p1 = __floats2half2_rn(tile[c_loc + 2][w_loc], tile[c_loc + 3][w_loc]);
        u32 base = ((b * Hh + h) * Ww + bxw * 32 + w_loc) * Cn + byc * 32 + c_loc;
        *(uint2*)&g_xt[base] = make_uint2(*(u32*)&p0, *(u32*)&p1);
    }
}

// ---------------------------------------------------------------
// Kernel 0b: weight re-layouts.
__global__ void k_transpose_w(const float* __restrict__ w_conv,
                              const float* __restrict__ w_p,
                              const float* __restrict__ w_m) {
    int t = blockIdx.x * blockDim.x + threadIdx.x;
    if (t < 9 * 4 * 16 * 32) {
        int l   = t & 31;
        int ob  = (t >> 5) & 15;
        int kk2 = (t >> 9) & 3;
        int k   = t >> 11;           // tap 0..8
        int o   = ob * 8 + (l >> 2);
        int cb  = (l & 3) * 2;
        int di = k / 3, dj = k - di * 3;
        __half hv[8];
#pragma unroll
        for (int q = 0; q < 2; q++) {
            int c0 = (kk2 * 2 + q) * 16 + cb;
            hv[q * 4 + 0] = __float2half(w_conv[((o * Cn + c0)     * 3 + di) * 3 + dj]);
            hv[q * 4 + 1] = __float2half(w_conv[((o * Cn + c0 + 1) * 3 + di) * 3 + dj]);
            hv[q * 4 + 2] = __float2half(w_conv[((o * Cn + c0 + 8) * 3 + di) * 3 + dj]);
            hv[q * 4 + 3] = __float2half(w_conv[((o * Cn + c0 + 9) * 3 + di) * 3 + dj]);
        }
        uint4 v;
        v.x = *(u32*)&hv[0]; v.y = *(u32*)&hv[2];
        v.z = *(u32*)&hv[4]; v.w = *(u32*)&hv[6];
        g_wd2[((k * 4 + kk2) * 16 + ob) * 32 + l] = v;
    } else {
        int t2 = t - 9 * 4 * 16 * 32;
        if (t2 < 9 * 27 * 128) {
            int c = t2 & 127;
            int rest = t2 >> 7;
            int o = rest % 27;
            int k = rest / 27;
            int kh = k / 3, kw = k - kh * 3;
            float val;
            if (o < 18) val = w_p[((o * Cn + c) * 3 + kh) * 3 + kw];
            else        val = w_m[(((o - 18) * Cn + c) * 3 + kh) * 3 + kw];
            g_wa[(k * 32 + o) * 136 + c] = __float2half(val);
        }
    }
}

// stage tap-k convA weights (8704 B = 544 x 16B) via cp.async (256 thr)
__device__ __forceinline__ void cp_bA(u32 dst, int k, int tid) {
    const char* src = (const char*)g_wa + k * CA_B_BYTES;
#pragma unroll
    for (int i = 0; i < 3; i++) {
        int idx = tid + i * 256;
        if (idx < 544) {
            asm volatile("cp.async.cg.shared.global [%0], [%1], 16;"
                         :: "r"(dst + (u32)idx * 16u), "l"(src + idx * 16) : "memory");
        }
    }
    asm volatile("cp.async.commit_group;" ::: "memory");
}

// ---------------------------------------------------------------
// Kernel A: fused offset(18)+mask(9) 3x3 conv (fp16 mma + smem halo),
// epilogue emits deformable-gather metadata per (px, n).
__global__ void __launch_bounds__(256, 2) k_convA(const float* __restrict__ b_p,
                                                  const float* __restrict__ b_m) {
    extern __shared__ char smc[];
    u32 Sb = smem_u32(smc);
    u32 Bbase = Sb + CA_HALO_BYTES;

    int b  = blockIdx.z;
    int h0 = blockIdx.y * 8, w0 = blockIdx.x * 16;
    int tid = threadIdx.x;
    int lane = tid & 31, wid = tid >> 5;   // 8 warps

    cp_bA(Bbase, 0, tid);

    // halo copy: 180 rows, fp16 direct (lane -> 4 channels = 8B)
    const uint2* xt2 = (const uint2*)g_xt;
    for (int r = wid; r < 180; r += 8) {
        int hy = r / 18, hx = r - hy * 18;
        int h = h0 - 1 + hy, w = w0 - 1 + hx;
        uint2 v = make_uint2(0u, 0u);
        if (h >= 0 && h < Hh && w >= 0 && w < Ww)
            v = xt2[((b * Hh + h) * Ww + w) * 32 + lane];
        *(uint2*)(smc + r * STRIDE_B + lane * 8) = v;
    }
    asm volatile("cp.async.wait_group 0;" ::: "memory");
    __syncthreads();

    float acc[16];
#pragma unroll
    for (int i = 0; i < 16; i++) acc[i] = 0.f;

    int mrow = wid * 16;
    int px_l = mrow + (lane & 15);
    int ly_l = px_l >> 4, lx_l = px_l & 15;
    u32 a_chunk = (u32)(lane >> 4) * 16u;
    u32 b_off = (u32)((lane & 7) + ((lane >> 4) << 3)) * STRIDE_B
              + (u32)((lane >> 3) & 1) * 16u;

#pragma unroll 1
    for (int t9 = 0; t9 < 9; t9++) {
        int kh = t9 / 3, kw = t9 - kh * 3;
        if (t9 < 8) cp_bA(Bbase + (u32)(((t9 + 1) & 1) * CA_B_BYTES), t9 + 1, tid);
        u32 Bcur = Bbase + (u32)((t9 & 1) * CA_B_BYTES);
        u32 a_base = (u32)((ly_l + kh) * 18 + lx_l + kw) * STRIDE_B + a_chunk;

#pragma unroll 1
        for (int kk = 0; kk < 8; kk++) {
            u32 koff = (u32)kk * 32u;
            u32 a[4], b0[4], b1[4];
            ldm4(Sb + a_base + koff, a);
            ldm4(Bcur + b_off + koff, b0);
            ldm4(Bcur + b_off + 16u * STRIDE_B + koff, b1);
            mma16816f(acc + 0,  a, b0[0], b0[1]);
            mma16816f(acc + 4,  a, b0[2], b0[3]);
            mma16816f(acc + 8,  a, b1[0], b1[1]);
            mma16816f(acc + 12, a, b1[2], b1[3]);
        }
        if (t9 < 8) {
            asm volatile("cp.async.wait_group 0;" ::: "memory");
            __syncthreads();
        }
    }
    __syncthreads();

    // epilogue 1: frags -> dsm[px][33]
    float* dsm = (float*)smc;
    {
        int g = lane >> 2, t = lane & 3;
#pragma unroll
        for (int si = 0; si < 4; si++) {
            int ob = si * 8;
            dsm[(mrow + g)     * 33 + ob + 2 * t]     = acc[si * 4 + 0];
            dsm[(mrow + g)     * 33 + ob + 2 * t + 1] = acc[si * 4 + 1];
            dsm[(mrow + g + 8) * 33 + ob + 2 * t]     = acc[si * 4 + 2];
            dsm[(mrow + g + 8) * 33 + ob + 2 * t + 1] = acc[si * 4 + 3];
        }
    }
    __syncthreads();

    // epilogue 2: bias + sigmoid + bilinear meta -> g_meta
    for (int idx = tid; idx < 128 * 9; idx += 256) {
        int px = idx / 9, n = idx - px * 9;
        float offx = dsm[px * 33 + n]      + b_p[n];
        float offy = dsm[px * 33 + 9 + n]  + b_p[9 + n];
        float mval = 1.f / (1.f + expf(-(dsm[px * 33 + 18 + n] + b_m[n])));
        int h = h0 + (px >> 4), w = w0 + (px & 15);
        int iI = n / 3, jJ = n - iI * 3;
        float p_x = offx + (float)(iI - 1) + (float)(h + 1);
        float p_y = offy + (float)(jJ - 1) + (float)(w + 1);
        float flx = floorf(p_x), fly = floorf(p_y);
        float ltx = fminf(fmaxf(flx, 0.f), 129.f);
        float lty = fminf(fmaxf(fly, 0.f), 129.f);
        float rbx = fminf(fmaxf(flx + 1.f, 0.f), 129.f);
        float rby = fminf(fmaxf(fly + 1.f, 0.f), 129.f);
        float cpx = fminf(fmaxf(p_x, 0.f), 129.f);
        float cpy = fminf(fmaxf(p_y, 0.f), 129.f);
        float ax  = 1.f + (ltx - cpx);
        float bx_ = 1.f - (rbx - cpx);
        float ay  = 1.f + (lty - cpy);
        float by_ = 1.f - (rby - cpy);
        float wq[4] = { ax * ay * mval, bx_ * by_ * mval, ax * by_ * mval, bx_ * ay * mval };
        float qxf[4] = { ltx, rbx, ltx, rbx };
        float qyf[4] = { lty, rby, rby, lty };
        int4 bs;
        int* bsp = &bs.x;
#pragma unroll
        for (int j = 0; j < 4; j++) {
            int ix = (int)qxf[j], iy = (int)qyf[j];
            bool valid = (ix >= 1 && ix <= Hh && iy >= 1 && iy <= Ww);
            bsp[j] = valid ? (((b * Hh + ix - 1) * Ww + iy - 1) * 256) : 0;
            if (!valid) wq[j] = 0.f;
        }
        int4* mp = (int4*)&g_meta[(((b * Hh + h) * Ww + w) * 9 + n) * 8];
        mp[0] = bs;
        __half2 w01 = __floats2half2_rn(wq[0], wq[1]);
        __half2 w23 = __floats2half2_rn(wq[2], wq[3]);
        ((uint2*)mp)[2] = make_uint2(*(u32*)&w01, *(u32*)&w23);
    }
}

// ---------------------------------------------------------------
// Prefetch ALL meta records this CTA needs (9 taps x 64 px, 32B each)
// into smem via cp.async, indexed [k][px].
__device__ __forceinline__ void prefetch_meta(int b, int oh0, int ow0,
                                              int tid, u32 MetaB) {
#pragma unroll
    for (int i = 0; i < 2; i++) {
        int r = tid + i * 512;
        if (r < 576) {
            int k = r >> 6, px = r & 63;
            int di = k / 3, dj = k - di * 3;
            int dh = (di == 0) ? -1 : 0;
            int iI = (di == 0) ? 2 : (di == 1 ? 0 : 1);
            int dw = (dj == 0) ? -1 : 0;
            int jJ = (dj == 0) ? 2 : (dj == 1 ? 0 : 1);
            int n = iI * 3 + jJ;
            int h = oh0 + (px >> 4) + dh, w = ow0 + (px & 15) + dw;
            const char* src = (const char*)g_meta;   // dummy for OOB (never read)
            if (h >= 0 && w >= 0)
                src = (const char*)&g_meta[(((b * Hh + h) * Ww + w) * 9 + n) * 8];
            u32 dst = MetaB + (u32)r * 32u;
            asm volatile("cp.async.cg.shared.global [%0], [%1], 16;"
                         :: "r"(dst), "l"(src) : "memory");
            asm volatile("cp.async.cg.shared.global [%0], [%1], 16;"
                         :: "r"(dst + 16u), "l"(src + 16) : "memory");
        }
    }
    asm volatile("cp.async.commit_group;" ::: "memory");
}

// ---------------------------------------------------------------
// Deform gather (smem-meta, packed half2): one conv-tap k, 64-px tile.
// Per pixel: 2 LDS (meta) + 4 independent corner LDG.64 + 8 HFMA2 + 1 STS.
__device__ __forceinline__ void gather_tapD(int b, int k, int oh0, int ow0,
                                            int lane, int wid, u32 MetaB, char* Adst) {
    const char* xb = (const char*)g_xt + lane * 8;
    int di = k / 3, dj = k - di * 3;
    int dh = (di == 0) ? -1 : 0;
    int dw = (dj == 0) ? -1 : 0;
#pragma unroll
    for (int s = 0; s < 4; s++) {
        int px = wid * 4 + s;
        int h = oh0 + (px >> 4) + dh, w = ow0 + (px & 15) + dw;
        __half2 a01 = __float2half2_rn(0.f), a23 = __float2half2_rn(0.f);
        if (h >= 0 && w >= 0) {
            u32 ma = MetaB + (u32)(k * 64 + px) * 32u;
            int4 bs; uint2 wp;
            asm("ld.shared.v4.s32 {%0,%1,%2,%3}, [%4];"
                : "=r"(bs.x), "=r"(bs.y), "=r"(bs.z), "=r"(bs.w) : "r"(ma));
            asm("ld.shared.v2.u32 {%0,%1}, [%2];"
                : "=r"(wp.x), "=r"(wp.y) : "r"(ma + 16u));
            __half2 w01 = *(__half2*)&wp.x;
            __half2 w23 = *(__half2*)&wp.y;
            __half2 wb0 = __half2half2(__low2half(w01));
            __half2 wb1 = __half2half2(__high2half(w01));
            __half2 wb2 = __half2half2(__low2half(w23));
            __half2 wb3 = __half2half2(__high2half(w23));
            uint2 q0 = *(const uint2*)(xb + bs.x);
            uint2 q1 = *(const uint2*)(xb + bs.y);
            uint2 q2 = *(const uint2*)(xb + bs.z);
            uint2 q3 = *(const uint2*)(xb + bs.w);
            a01 = __hfma2(wb0, *(__half2*)&q0.x, a01);
            a23 = __hfma2(wb0, *(__half2*)&q0.y, a23);
            a01 = __hfma2(wb1, *(__half2*)&q1.x, a01);
            a23 = __hfma2(wb1, *(__half2*)&q1.y, a23);
            a01 = __hfma2(wb2, *(__half2*)&q2.x, a01);
            a23 = __hfma2(wb2, *(__half2*)&q2.y, a23);
            a01 = __hfma2(wb3, *(__half2*)&q3.x, a01);
            a23 = __hfma2(wb3, *(__half2*)&q3.y, a23);
        }
        *(uint2*)(Adst + px * STRIDE_B + lane * 8) = make_uint2(*(u32*)&a01, *(u32*)&a23);
    }
}

// Deform MMA for one tap: warp = 16px x 32o; A via ldmatrix, B via direct
// register-fragment LDG.128 from the pre-swizzled g_wd2 blob (L1-resident).
__device__ __forceinline__ void mma_tapD(u32 Acur, const uint4* __restrict__ Bp,
                                         u32 a_off, int ob0, int lane, float* acc) {
#pragma unroll 1
    for (int kk2 = 0; kk2 < 4; kk2++) {
        u32 koff = (u32)kk2 * 64u;
        u32 aE[4], aO[4];
        ldm4(Acur + a_off + koff, aE);
        ldm4(Acur + a_off + koff + 32u, aO);
        const uint4* bq = Bp + (kk2 * 16 + ob0) * 32 + lane;
        uint4 b0 = __ldg(bq);
        uint4 b1 = __ldg(bq + 32);
        uint4 b2 = __ldg(bq + 64);
        uint4 b3 = __ldg(bq + 96);
        mma16816f(acc + 0,  aE, b0.x, b0.y);
        mma16816f(acc + 4,  aE, b1.x, b1.y);
        mma16816f(acc + 8,  aE, b2.x, b2.y);
        mma16816f(acc + 12, aE, b3.x, b3.y);
        mma16816f(acc + 0,  aO, b0.z, b0.w);
        mma16816f(acc + 4,  aO, b1.z, b1.w);
        mma16816f(acc + 8,  aO, b2.z, b2.w);
        mma16816f(acc + 12, aO, b3.z, b3.w);
    }
}

// ---------------------------------------------------------------
// Kernel B: smem-meta deformable gather -> fp16 mma.sync GEMM.
// Block 512 / 16 warps; tile M=64 px (4h x 16w) x N=128 o; 2 CTAs/SM.
// A double-buffered in smem; meta prefetched via cp.async; B streamed as
// global register-fragments.
__global__ void __launch_bounds__(512, 2) k_deform(float* __restrict__ out) {
    extern __shared__ char smc[];
    u32 Sb = smem_u32(smc);
    u32 MetaB = Sb + (u32)D_META_OFF;

    int b   = blockIdx.z;
    int oh0 = blockIdx.y * 4, ow0 = blockIdx.x * 16;
    int tid  = threadIdx.x;
    int lane = tid & 31, wid = tid >> 5;
    int mrow = (wid & 3) * 16;
    int ob0  = (wid >> 2) * 4;      // o-block base (o = ob0*8)

    float acc[16];
#pragma unroll
    for (int i = 0; i < 16; i++) acc[i] = 0.f;

    u32 a_off = (u32)(mrow + (lane & 15)) * STRIDE_B + (u32)(lane >> 4) * 16u;

    // prologue: prefetch all meta, then gather tap 0 into A0
    prefetch_meta(b, oh0, ow0, tid, MetaB);
    asm volatile("cp.async.wait_group 0;" ::: "memory");
    __syncthreads();
    gather_tapD(b, 0, oh0, ow0, lane, wid, MetaB, smc);
    __syncthreads();

#pragma unroll 1
    for (int k = 0; k < 9; k++) {
        int cur = k & 1;
        u32 Acur = Sb + (u32)cur * D_A_BYTES;
        char* Anxt = smc + (cur ^ 1) * D_A_BYTES;
        const uint4* Bp = g_wd2 + k * 2048;

        if (wid & 1) {
            if (k < 8) gather_tapD(b, k + 1, oh0, ow0, lane, wid, MetaB, Anxt);
            mma_tapD(Acur, Bp, a_off, ob0, lane, acc);
        } else {
            mma_tapD(Acur, Bp, a_off, ob0, lane, acc);
            if (k < 8) gather_tapD(b, k + 1, oh0, ow0, lane, wid, MetaB, Anxt);
        }
        __syncthreads();
    }

    // epilogue: direct global stores
    {
        int g = lane >> 2, t = lane & 3;
        int oh = oh0 + (mrow >> 4);
        int ow1 = ow0 + g, ow2 = ow0 + g + 8;
        int nb = ob0 * 8;
#pragma unroll
        for (int si = 0; si < 4; si++) {
            int o0 = nb + si * 8 + 2 * t;
            float* r0 = &out[((b * OC + o0) * Hh + oh) * Ww];
            float* r1 = &out[((b * OC + o0 + 1) * Hh + oh) * Ww];
            r0[ow1] = acc[si * 4 + 0];
            r1[ow1] = acc[si * 4 + 1];
            r0[ow2] = acc[si * 4 + 2];
            r1[ow2] = acc[si * 4 + 3];
        }
    }
}

// ---------------------------------------------------------------
extern "C" void kernel_launch(void* const* d_in, const int* in_sizes, int n_in,
                              void* d_out, int out_size) {
    const float* x      = (const float*)d_in[0];
    const float* w_p    = (const float*)d_in[1];
    const float* b_p    = (const float*)d_in[2];
    const float* w_m    = (const float*)d_in[3];
    const float* b_m    = (const float*)d_in[4];
    const float* w_conv = (const float*)d_in[5];
    float* out = (float*)d_out;

    cudaFuncSetAttribute(k_convA,  cudaFuncAttributeMaxDynamicSharedMemorySize, CA_SMEM);
    cudaFuncSetAttribute(k_deform, cudaFuncAttributeMaxDynamicSharedMemorySize, D_SMEM);

    k_transpose_x<<<dim3(4, 4, Bn * Hh), dim3(32, 8)>>>(x);

    int wthreads = 9 * 4 * 16 * 32 + 9 * 27 * 128;
    k_transpose_w<<<(wthreads + 255) / 256, 256>>>(w_conv, w_p, w_m);

    // convA: tile 8(h) x 16(w): grid (8, 16, B) = 256 CTAs
    k_convA<<<dim3(8, 16, Bn), 256, CA_SMEM>>>(b_p, b_m);

    // deform: tile 4(h) x 16(w): grid (8, 32, B) = 512 CTAs
    k_deform<<<dim3(8, 32, Bn), 512, D_SMEM>>>(out);
}

// round 15
// speedup vs baseline: 2.7090x; 1.0222x over previous
#include <cuda_runtime.h>
#include <cuda_fp16.h>
#include <math.h>

// Problem constants: B=2, C=128, H=W=128, outc=128, KS=3, N=9, PAD=1
#define Bn 2
#define Cn 128
#define Hh 128
#define Ww 128
#define OC 128

typedef unsigned long long u64;
typedef unsigned int u32;

// -------- scratch (static device globals; no allocation allowed) --------
__device__ __half g_xt [Bn*Hh*Ww*Cn];              // x as fp16 [B,H,W,C]
// per (b,h,w,n) gather meta (32B): {int4 corner byte-offsets, half2 w01, half2 w23, 8B pad}
__device__ __align__(16) int g_meta[Bn*Hh*Ww*9*8]; // 9.4 MB
// deform W pre-swizzled into mma.sync B-fragment order:
// uint4 index ((k*4+kk2)*16+ob)*32+lane ; .x/.y = kk even regs, .z/.w = kk odd
__device__ __align__(16) uint4 g_wd2[9*2048];      // 288 KB
__device__ __align__(16) __half g_wa[9*32*136];    // convA W fp16 [k][o(27)][c]; rows 27-31 zero

#define STRIDE_B 272                 // 136 fp16 per row
#define D_A_BYTES 8704               // 32 rows
#define D_META_OFF (2*8704)          // meta after A0/A1
#define D_SMEM (2*8704 + 288*32)     // 26624

#define CA_HALO_BYTES (180*272)      // 48960 (10h x 18w halo rows)
#define CA_B_BYTES 8704              // 32 rows
#define CA_SMEM (48960 + 2*8704)     // 66368

__device__ __forceinline__ u32 smem_u32(const void* p) {
    u32 a;
    asm("{ .reg .u64 t; cvta.to.shared.u64 t, %1; cvt.u32.u64 %0, t; }" : "=r"(a) : "l"(p));
    return a;
}

__device__ __forceinline__ void ldm4(u32 addr, u32* r) {
    asm volatile("ldmatrix.sync.aligned.m8n8.x4.shared.b16 {%0,%1,%2,%3}, [%4];"
                 : "=r"(r[0]), "=r"(r[1]), "=r"(r[2]), "=r"(r[3]) : "r"(addr));
}

__device__ __forceinline__ void mma16816f(float* c, const u32* a, u32 b0, u32 b1) {
    asm volatile("mma.sync.aligned.m16n8k16.row.col.f32.f16.f16.f32 "
                 "{%0,%1,%2,%3}, {%4,%5,%6,%7}, {%8,%9}, {%0,%1,%2,%3};"
                 : "+f"(c[0]), "+f"(c[1]), "+f"(c[2]), "+f"(c[3])
                 : "r"(a[0]), "r"(a[1]), "r"(a[2]), "r"(a[3]), "r"(b0), "r"(b1));
}

// ---------------------------------------------------------------
// Kernel 0 (merged): block id < 4096 -> transpose x NCHW->BHWC (fp16);
// otherwise -> weight re-layouts (g_wd2 fragment blob + g_wa rows).
__global__ void k_pre(const float* __restrict__ x,
                      const float* __restrict__ w_conv,
                      const float* __restrict__ w_p,
                      const float* __restrict__ w_m) {
    int blk = blockIdx.x;
    int tid = threadIdx.x;
    if (blk < 4096) {
        __shared__ float tile[32][33];
        int bxw = blk & 3, byc = (blk >> 2) & 3, bz = blk >> 4;
        int b = bz >> 7, h = bz & 127;
        int tx = tid & 31, ty = tid >> 5;
#pragma unroll
        for (int i = 0; i < 4; i++) {
            int c = byc * 32 + ty + i * 8;
            tile[ty + i * 8][tx] = x[((b * Cn + c) * Hh + h) * Ww + bxw * 32 + tx];
        }
        __syncthreads();
        {
            int w_loc = tid >> 3, c_loc = (tid & 7) * 4;
            __half2 p0 = __floats2half2_rn(tile[c_loc + 0][w_loc], tile[c_loc + 1][w_loc]);
            __half2 p1 = __floats2half2_rn(tile[c_loc + 2][w_loc], tile[c_loc + 3][w_loc]);
            u32 base = ((b * Hh + h) * Ww + bxw * 32 + w_loc) * Cn + byc * 32 + c_loc;
            *(uint2*)&g_xt[base] = make_uint2(*(u32*)&p0, *(u32*)&p1);
        }
    } else {
        int t = (blk - 4096) * 256 + tid;
        if (t < 9 * 4 * 16 * 32) {
            int l   = t & 31;
            int ob  = (t >> 5) & 15;
            int kk2 = (t >> 9) & 3;
            int k   = t >> 11;           // tap 0..8
            int o   = ob * 8 + (l >> 2);
            int cb  = (l & 3) * 2;
            int di = k / 3, dj = k - di * 3;
            __half hv[8];
#pragma unroll
            for (int q = 0; q < 2; q++) {
                int c0 = (kk2 * 2 + q) * 16 + cb;
                hv[q * 4 + 0] = __float2half(w_conv[((o * Cn + c0)     * 3 + di) * 3 + dj]);
                hv[q * 4 + 1] = __float2half(w_conv[((o * Cn + c0 + 1) * 3 + di) * 3 + dj]);
                hv[q * 4 + 2] = __float2half(w_conv[((o * Cn + c0 + 8) * 3 + di) * 3 + dj]);
                hv[q * 4 + 3] = __float2half(w_conv[((o * Cn + c0 + 9) * 3 + di) * 3 + dj]);
            }
            uint4 v;
            v.x = *(u32*)&hv[0]; v.y = *(u32*)&hv[2];
            v.z = *(u32*)&hv[4]; v.w = *(u32*)&hv[6];
            g_wd2[((k * 4 + kk2) * 16 + ob) * 32 + l] = v;
        } else {
            int t2 = t - 9 * 4 * 16 * 32;
            if (t2 < 9 * 27 * 128) {
                int c = t2 & 127;
                int rest = t2 >> 7;
                int o = rest % 27;
                int k = rest / 27;
                int kh = k / 3, kw = k - kh * 3;
                float val;
                if (o < 18) val = w_p[((o * Cn + c) * 3 + kh) * 3 + kw];
                else        val = w_m[(((o - 18) * Cn + c) * 3 + kh) * 3 + kw];
                g_wa[(k * 32 + o) * 136 + c] = __float2half(val);
            }
        }
    }
}

// stage tap-k convA weights (8704 B = 544 x 16B) via cp.async (256 thr)
__device__ __forceinline__ void cp_bA(u32 dst, int k, int tid) {
    const char* src = (const char*)g_wa + k * CA_B_BYTES;
#pragma unroll
    for (int i = 0; i < 3; i++) {
        int idx = tid + i * 256;
        if (idx < 544) {
            asm volatile("cp.async.cg.shared.global [%0], [%1], 16;"
                         :: "r"(dst + (u32)idx * 16u), "l"(src + idx * 16) : "memory");
        }
    }
    asm volatile("cp.async.commit_group;" ::: "memory");
}

// ---------------------------------------------------------------
// Kernel A: fused offset(18)+mask(9) 3x3 conv (fp16 mma + smem halo),
// epilogue emits deformable-gather metadata per (px, n).
__global__ void __launch_bounds__(256, 2) k_convA(const float* __restrict__ b_p,
                                                  const float* __restrict__ b_m) {
    extern __shared__ char smc[];
    u32 Sb = smem_u32(smc);
    u32 Bbase = Sb + CA_HALO_BYTES;

    int b  = blockIdx.z;
    int h0 = blockIdx.y * 8, w0 = blockIdx.x * 16;
    int tid = threadIdx.x;
    int lane = tid & 31, wid = tid >> 5;   // 8 warps

    cp_bA(Bbase, 0, tid);

    // halo copy: 180 rows, fp16 direct (lane -> 4 channels = 8B)
    const uint2* xt2 = (const uint2*)g_xt;
    for (int r = wid; r < 180; r += 8) {
        int hy = r / 18, hx = r - hy * 18;
        int h = h0 - 1 + hy, w = w0 - 1 + hx;
        uint2 v = make_uint2(0u, 0u);
        if (h >= 0 && h < Hh && w >= 0 && w < Ww)
            v = xt2[((b * Hh + h) * Ww + w) * 32 + lane];
        *(uint2*)(smc + r * STRIDE_B + lane * 8) = v;
    }
    asm volatile("cp.async.wait_group 0;" ::: "memory");
    __syncthreads();

    float acc[16];
#pragma unroll
    for (int i = 0; i < 16; i++) acc[i] = 0.f;

    int mrow = wid * 16;
    int px_l = mrow + (lane & 15);
    int ly_l = px_l >> 4, lx_l = px_l & 15;
    u32 a_chunk = (u32)(lane >> 4) * 16u;
    u32 b_off = (u32)((lane & 7) + ((lane >> 4) << 3)) * STRIDE_B
              + (u32)((lane >> 3) & 1) * 16u;

#pragma unroll 1
    for (int t9 = 0; t9 < 9; t9++) {
        int kh = t9 / 3, kw = t9 - kh * 3;
        if (t9 < 8) cp_bA(Bbase + (u32)(((t9 + 1) & 1) * CA_B_BYTES), t9 + 1, tid);
        u32 Bcur = Bbase + (u32)((t9 & 1) * CA_B_BYTES);
        u32 a_base = (u32)((ly_l + kh) * 18 + lx_l + kw) * STRIDE_B + a_chunk;

#pragma unroll 1
        for (int kk = 0; kk < 8; kk++) {
            u32 koff = (u32)kk * 32u;
            u32 a[4], b0[4], b1[4];
            ldm4(Sb + a_base + koff, a);
            ldm4(Bcur + b_off + koff, b0);
            ldm4(Bcur + b_off + 16u * STRIDE_B + koff, b1);
            mma16816f(acc + 0,  a, b0[0], b0[1]);
            mma16816f(acc + 4,  a, b0[2], b0[3]);
            mma16816f(acc + 8,  a, b1[0], b1[1]);
            mma16816f(acc + 12, a, b1[2], b1[3]);
        }
        if (t9 < 8) {
            asm volatile("cp.async.wait_group 0;" ::: "memory");
            __syncthreads();
        }
    }
    __syncthreads();

    // epilogue 1: frags -> dsm[px][33]
    float* dsm = (float*)smc;
    {
        int g = lane >> 2, t = lane & 3;
#pragma unroll
        for (int si = 0; si < 4; si++) {
            int ob = si * 8;
            dsm[(mrow + g)     * 33 + ob + 2 * t]     = acc[si * 4 + 0];
            dsm[(mrow + g)     * 33 + ob + 2 * t + 1] = acc[si * 4 + 1];
            dsm[(mrow + g + 8) * 33 + ob + 2 * t]     = acc[si * 4 + 2];
            dsm[(mrow + g + 8) * 33 + ob + 2 * t + 1] = acc[si * 4 + 3];
        }
    }
    __syncthreads();

    // epilogue 2: bias + sigmoid + bilinear meta -> g_meta
    for (int idx = tid; idx < 128 * 9; idx += 256) {
        int px = idx / 9, n = idx - px * 9;
        float offx = dsm[px * 33 + n]      + b_p[n];
        float offy = dsm[px * 33 + 9 + n]  + b_p[9 + n];
        float mval = 1.f / (1.f + expf(-(dsm[px * 33 + 18 + n] + b_m[n])));
        int h = h0 + (px >> 4), w = w0 + (px & 15);
        int iI = n / 3, jJ = n - iI * 3;
        float p_x = offx + (float)(iI - 1) + (float)(h + 1);
        float p_y = offy + (float)(jJ - 1) + (float)(w + 1);
        float flx = floorf(p_x), fly = floorf(p_y);
        float ltx = fminf(fmaxf(flx, 0.f), 129.f);
        float lty = fminf(fmaxf(fly, 0.f), 129.f);
        float rbx = fminf(fmaxf(flx + 1.f, 0.f), 129.f);
        float rby = fminf(fmaxf(fly + 1.f, 0.f), 129.f);
        float cpx = fminf(fmaxf(p_x, 0.f), 129.f);
        float cpy = fminf(fmaxf(p_y, 0.f), 129.f);
        float ax  = 1.f + (ltx - cpx);
        float bx_ = 1.f - (rbx - cpx);
        float ay  = 1.f + (lty - cpy);
        float by_ = 1.f - (rby - cpy);
        float wq[4] = { ax * ay * mval, bx_ * by_ * mval, ax * by_ * mval, bx_ * ay * mval };
        float qxf[4] = { ltx, rbx, ltx, rbx };
        float qyf[4] = { lty, rby, rby, lty };
        int4 bs;
        int* bsp = &bs.x;
#pragma unroll
        for (int j = 0; j < 4; j++) {
            int ix = (int)qxf[j], iy = (int)qyf[j];
            bool valid = (ix >= 1 && ix <= Hh && iy >= 1 && iy <= Ww);
            bsp[j] = valid ? (((b * Hh + ix - 1) * Ww + iy - 1) * 256) : 0;
            if (!valid) wq[j] = 0.f;
        }
        int4* mp = (int4*)&g_meta[(((b * Hh + h) * Ww + w) * 9 + n) * 8];
        mp[0] = bs;
        __half2 w01 = __floats2half2_rn(wq[0], wq[1]);
        __half2 w23 = __floats2half2_rn(wq[2], wq[3]);
        ((uint2*)mp)[2] = make_uint2(*(u32*)&w01, *(u32*)&w23);
    }
}

// ---------------------------------------------------------------
// Prefetch ALL meta records this CTA needs (9 taps x 32 px, 32B each)
// into smem via cp.async, indexed [k][px].
__device__ __forceinline__ void prefetch_meta(int b, int oh0, int ow0,
                                              int tid, u32 MetaB) {
#pragma unroll
    for (int i = 0; i < 2; i++) {
        int r = tid + i * 256;
        if (r < 288) {
            int k = r >> 5, px = r & 31;
            int di = k / 3, dj = k - di * 3;
            int dh = (di == 0) ? -1 : 0;
            int iI = (di == 0) ? 2 : (di == 1 ? 0 : 1);
            int dw = (dj == 0) ? -1 : 0;
            int jJ = (dj == 0) ? 2 : (dj == 1 ? 0 : 1);
            int n = iI * 3 + jJ;
            int h = oh0 + (px >> 4) + dh, w = ow0 + (px & 15) + dw;
            const char* src = (const char*)g_meta;   // dummy for OOB (never read)
            if (h >= 0 && w >= 0)
                src = (const char*)&g_meta[(((b * Hh + h) * Ww + w) * 9 + n) * 8];
            u32 dst = MetaB + (u32)r * 32u;
            asm volatile("cp.async.cg.shared.global [%0], [%1], 16;"
                         :: "r"(dst), "l"(src) : "memory");
            asm volatile("cp.async.cg.shared.global [%0], [%1], 16;"
                         :: "r"(dst + 16u), "l"(src + 16) : "memory");
        }
    }
    asm volatile("cp.async.commit_group;" ::: "memory");
}

// ---------------------------------------------------------------
// Deform gather (smem-meta, packed half2): one conv-tap k, 32-px tile.
// 8 warps x 4 px; per pixel: 2 LDS (meta) + 4 corner LDG.64 + 8 HFMA2 + 1 STS.
__device__ __forceinline__ void gather_tapD(int b, int k, int oh0, int ow0,
                                            int lane, int wid, u32 MetaB, char* Adst) {
    const char* xb = (const char*)g_xt + lane * 8;
    int di = k / 3, dj = k - di * 3;
    int dh = (di == 0) ? -1 : 0;
    int dw = (dj == 0) ? -1 : 0;
#pragma unroll
    for (int s = 0; s < 4; s++) {
        int px = wid * 4 + s;
        int h = oh0 + (px >> 4) + dh, w = ow0 + (px & 15) + dw;
        __half2 a01 = __float2half2_rn(0.f), a23 = __float2half2_rn(0.f);
        if (h >= 0 && w >= 0) {
            u32 ma = MetaB + (u32)(k * 32 + px) * 32u;
            int4 bs; uint2 wp;
            asm("ld.shared.v4.s32 {%0,%1,%2,%3}, [%4];"
                : "=r"(bs.x), "=r"(bs.y), "=r"(bs.z), "=r"(bs.w) : "r"(ma));
            asm("ld.shared.v2.u32 {%0,%1}, [%2];"
                : "=r"(wp.x), "=r"(wp.y) : "r"(ma + 16u));
            __half2 w01 = *(__half2*)&wp.x;
            __half2 w23 = *(__half2*)&wp.y;
            __half2 wb0 = __half2half2(__low2half(w01));
            __half2 wb1 = __half2half2(__high2half(w01));
            __half2 wb2 = __half2half2(__low2half(w23));
            __half2 wb3 = __half2half2(__high2half(w23));
            uint2 q0 = *(const uint2*)(xb + bs.x);
            uint2 q1 = *(const uint2*)(xb + bs.y);
            uint2 q2 = *(const uint2*)(xb + bs.z);
            uint2 q3 = *(const uint2*)(xb + bs.w);
            a01 = __hfma2(wb0, *(__half2*)&q0.x, a01);
            a23 = __hfma2(wb0, *(__half2*)&q0.y, a23);
            a01 = __hfma2(wb1, *(__half2*)&q1.x, a01);
            a23 = __hfma2(wb1, *(__half2*)&q1.y, a23);
            a01 = __hfma2(wb2, *(__half2*)&q2.x, a01);
            a23 = __hfma2(wb2, *(__half2*)&q2.y, a23);
            a01 = __hfma2(wb3, *(__half2*)&q3.x, a01);
            a23 = __hfma2(wb3, *(__half2*)&q3.y, a23);
        }
        *(uint2*)(Adst + px * STRIDE_B + lane * 8) = make_uint2(*(u32*)&a01, *(u32*)&a23);
    }
}

// Deform MMA for one tap: warp = 16px x 32o; A via ldmatrix, B via direct
// register-fragment LDG.128 from the pre-swizzled g_wd2 blob (L1-resident).
__device__ __forceinline__ void mma_tapD(u32 Acur, const uint4* __restrict__ Bp,
                                         u32 a_off, int ob0, int lane, float* acc) {
#pragma unroll 1
    for (int kk2 = 0; kk2 < 4; kk2++) {
        u32 koff = (u32)kk2 * 64u;
        u32 aE[4], aO[4];
        ldm4(Acur + a_off + koff, aE);
        ldm4(Acur + a_off + koff + 32u, aO);
        const uint4* bq = Bp + (kk2 * 16 + ob0) * 32 + lane;
        uint4 b0 = __ldg(bq);
        uint4 b1 = __ldg(bq + 32);
        uint4 b2 = __ldg(bq + 64);
        uint4 b3 = __ldg(bq + 96);
        mma16816f(acc + 0,  aE, b0.x, b0.y);
        mma16816f(acc + 4,  aE, b1.x, b1.y);
        mma16816f(acc + 8,  aE, b2.x, b2.y);
        mma16816f(acc + 12, aE, b3.x, b3.y);
        mma16816f(acc + 0,  aO, b0.z, b0.w);
        mma16816f(acc + 4,  aO, b1.z, b1.w);
        mma16816f(acc + 8,  aO, b2.z, b2.w);
        mma16816f(acc + 12, aO, b3.z, b3.w);
    }
}

// ---------------------------------------------------------------
// Kernel B: smem-meta deformable gather -> fp16 mma.sync GEMM.
// Block 256 / 8 warps; tile M=32 px (2h x 16w) x N=128 o; 4 CTAs/SM.
// A double-buffered; meta prefetched via cp.async; B streamed from global.
__global__ void __launch_bounds__(256, 4) k_deform(float* __restrict__ out) {
    extern __shared__ char smc[];
    u32 Sb = smem_u32(smc);
    u32 MetaB = Sb + (u32)D_META_OFF;

    int b   = blockIdx.z;
    int oh0 = blockIdx.y * 2, ow0 = blockIdx.x * 16;
    int tid  = threadIdx.x;
    int lane = tid & 31, wid = tid >> 5;
    int mrow = (wid & 1) * 16;
    int ob0  = (wid >> 1) * 4;      // o-block base (o = ob0*8)

    float acc[16];
#pragma unroll
    for (int i = 0; i < 16; i++) acc[i] = 0.f;

    u32 a_off = (u32)(mrow + (lane & 15)) * STRIDE_B + (u32)(lane >> 4) * 16u;

    // prologue: prefetch all meta, then gather tap 0 into A0
    prefetch_meta(b, oh0, ow0, tid, MetaB);
    asm volatile("cp.async.wait_group 0;" ::: "memory");
    __syncthreads();
    gather_tapD(b, 0, oh0, ow0, lane, wid, MetaB, smc);
    __syncthreads();

#pragma unroll 1
    for (int k = 0; k < 9; k++) {
        int cur = k & 1;
        u32 Acur = Sb + (u32)cur * D_A_BYTES;
        char* Anxt = smc + (cur ^ 1) * D_A_BYTES;
        const uint4* Bp = g_wd2 + k * 2048;

        if (wid & 1) {
            if (k < 8) gather_tapD(b, k + 1, oh0, ow0, lane, wid, MetaB, Anxt);
            mma_tapD(Acur, Bp, a_off, ob0, lane, acc);
        } else {
            mma_tapD(Acur, Bp, a_off, ob0, lane, acc);
            if (k < 8) gather_tapD(b, k + 1, oh0, ow0, lane, wid, MetaB, Anxt);
        }
        __syncthreads();
    }

    // epilogue: direct global stores
    {
        int g = lane >> 2, t = lane & 3;
        int oh = oh0 + (mrow >> 4);
        int ow1 = ow0 + g, ow2 = ow0 + g + 8;
        int nb = ob0 * 8;
#pragma unroll
        for (int si = 0; si < 4; si++) {
            int o0 = nb + si * 8 + 2 * t;
            float* r0 = &out[((b * OC + o0) * Hh + oh) * Ww];
            float* r1 = &out[((b * OC + o0 + 1) * Hh + oh) * Ww];
            r0[ow1] = acc[si * 4 + 0];
            r1[ow1] = acc[si * 4 + 1];
            r0[ow2] = acc[si * 4 + 2];
            r1[ow2] = acc[si * 4 + 3];
        }
    }
}

// ---------------------------------------------------------------
extern "C" void kernel_launch(void* const* d_in, const int* in_sizes, int n_in,
                              void* d_out, int out_size) {
    const float* x      = (const float*)d_in[0];
    const float* w_p    = (const float*)d_in[1];
    const float* b_p    = (const float*)d_in[2];
    const float* w_m    = (const float*)d_in[3];
    const float* b_m    = (const float*)d_in[4];
    const float* w_conv = (const float*)d_in[5];
    float* out = (float*)d_out;

    cudaFuncSetAttribute(k_convA,  cudaFuncAttributeMaxDynamicSharedMemorySize, CA_SMEM);
    cudaFuncSetAttribute(k_deform, cudaFuncAttributeMaxDynamicSharedMemorySize, D_SMEM);

    // merged transpose: 4096 x-blocks + 194 w-blocks
    int wthreads = 9 * 4 * 16 * 32 + 9 * 27 * 128;
    int wblocks = (wthreads + 255) / 256;
    k_pre<<<4096 + wblocks, 256>>>(x, w_conv, w_p, w_m);

    // convA: tile 8(h) x 16(w): grid (8, 16, B) = 256 CTAs
    k_convA<<<dim3(8, 16, Bn), 256, CA_SMEM>>>(b_p, b_m);

    // deform: tile 2(h) x 16(w): grid (8, 64, B) = 1024 CTAs
    k_deform<<<dim3(8, 64, Bn), 256, D_SMEM>>>(out);
}